// round 1
// baseline (speedup 1.0000x reference)
#include <cuda_runtime.h>
#include <math.h>

#define BB 4
#define NTOK 1024
#define CDIM 1024
#define NH 16
#define HD 64
#define KCL 8
#define NBH (BB*NH)          // 64
#define NROWS (BB*NH*NTOK)   // 65536
#define M_ALL (BB*NTOK)      // 4096

// ---------------- scratch (static device globals; no allocation) -------------
__device__ float g_q[NROWS*HD];
__device__ float g_k[NROWS*HD];
__device__ float g_v[NROWS*HD];
__device__ float g_S[(long long)NBH*NTOK*NTOK];   // 67108864 floats = 256MB
__device__ float g_oh[M_ALL*CDIM];
__device__ float g_z[NROWS*KCL];
__device__ float g_zB[NROWS*KCL];
__device__ float g_th[NROWS];
__device__ float g_zc;

// ---------------------------------------------------------------------------
__global__ void zero_zc_kernel() { g_zc = 0.0f; }

// ---------------- K1: QKV projection  x[4096,1024] @ Wqkv[1024,3072] --------
// 128x128 tile, BK=8, 256 threads, 8x8 per thread. Scatter into g_q/g_k/g_v.
__global__ __launch_bounds__(256) void qkv_gemm(const float* __restrict__ x,
                                                const float* __restrict__ W) {
    __shared__ float As[8][128];
    __shared__ float Bs[8][128];
    const int t  = threadIdx.x;
    const int tx = t & 15, ty = t >> 4;
    const int m0 = blockIdx.y * 128;
    const int n0 = blockIdx.x * 128;
    float acc[8][8];
    #pragma unroll
    for (int i = 0; i < 8; i++)
        #pragma unroll
        for (int j = 0; j < 8; j++) acc[i][j] = 0.0f;

    const int lm  = t >> 1, lkc = (t & 1) * 4;   // A loader: row lm, cols lkc..+3
    const int lkk = t >> 5, lc  = (t & 31) * 4;  // B loader

    for (int kt = 0; kt < 1024; kt += 8) {
        float4 av = *(const float4*)&x[(m0 + lm) * 1024 + kt + lkc];
        As[lkc + 0][lm] = av.x; As[lkc + 1][lm] = av.y;
        As[lkc + 2][lm] = av.z; As[lkc + 3][lm] = av.w;
        *(float4*)&Bs[lkk][lc] = *(const float4*)&W[(kt + lkk) * 3072 + n0 + lc];
        __syncthreads();
        #pragma unroll
        for (int kk = 0; kk < 8; kk++) {
            float4 a0 = *(float4*)&As[kk][ty * 8];
            float4 a1 = *(float4*)&As[kk][ty * 8 + 4];
            float4 b0 = *(float4*)&Bs[kk][tx * 8];
            float4 b1 = *(float4*)&Bs[kk][tx * 8 + 4];
            float a[8] = {a0.x,a0.y,a0.z,a0.w,a1.x,a1.y,a1.z,a1.w};
            float b[8] = {b0.x,b0.y,b0.z,b0.w,b1.x,b1.y,b1.z,b1.w};
            #pragma unroll
            for (int i = 0; i < 8; i++)
                #pragma unroll
                for (int j = 0; j < 8; j++) acc[i][j] += a[i] * b[j];
        }
        __syncthreads();
    }
    #pragma unroll
    for (int i = 0; i < 8; i++) {
        const int m = m0 + ty * 8 + i;
        const int b = m >> 10, n = m & 1023;
        #pragma unroll
        for (int j = 0; j < 8; j++) {
            const int col = n0 + tx * 8 + j;
            const int which = col >> 10;
            const int rem = col & 1023;
            const int h = rem >> 6, d = rem & 63;
            float* dst = (which == 0) ? g_q : (which == 1) ? g_k : g_v;
            dst[((b * NH + h) * NTOK + n) * HD + d] = acc[i][j];
        }
    }
}

// ---------------- K2: cluster softmax z, zB = z*sigmoid(B), theta -----------
__global__ __launch_bounds__(256) void zkernel(const float* __restrict__ Wg,
                                               const float* __restrict__ bg,
                                               const float* __restrict__ Wt,
                                               const float* __restrict__ bt,
                                               const float* __restrict__ affB) {
    const int r = blockIdx.x * 256 + threadIdx.x;
    const int h = (r >> 10) & (NH - 1);
    const float* q = g_q + r * HD;

    float g[KCL];
    #pragma unroll
    for (int l = 0; l < KCL; l++) g[l] = bg[l];
    float th = bt[0];
    for (int k = 0; k < HD; k++) {
        const float qv = q[k];
        th += qv * Wt[k];
        #pragma unroll
        for (int l = 0; l < KCL; l++) g[l] += qv * Wg[k * KCL + l];
    }
    float mx = g[0];
    #pragma unroll
    for (int l = 1; l < KCL; l++) mx = fmaxf(mx, g[l]);
    float s = 0.0f;
    #pragma unroll
    for (int l = 0; l < KCL; l++) { g[l] = __expf(g[l] - mx); s += g[l]; }
    const float inv = 1.0f / s;
    float ent = 0.0f;
    #pragma unroll
    for (int l = 0; l < KCL; l++) {
        const float z = g[l] * inv;
        g[l] = z;
        ent -= z * logf(z + 1e-8f);
    }
    float zB[KCL];
    #pragma unroll
    for (int l = 0; l < KCL; l++) zB[l] = 0.0f;
    #pragma unroll
    for (int k = 0; k < KCL; k++) {
        const float zk = g[k];
        #pragma unroll
        for (int l = 0; l < KCL; l++) {
            const float a = affB[h * 64 + k * KCL + l];
            const float sg = 1.0f / (1.0f + __expf(-a));
            zB[l] += zk * sg;
        }
    }
    g_th[r] = fmaxf(th, 0.0f);
    #pragma unroll
    for (int l = 0; l < KCL; l++) { g_z[r * KCL + l] = g[l]; g_zB[r * KCL + l] = zB[l]; }

    __shared__ float red[256];
    red[threadIdx.x] = ent;
    __syncthreads();
    for (int s2 = 128; s2 > 0; s2 >>= 1) {
        if (threadIdx.x < s2) red[threadIdx.x] += red[threadIdx.x + s2];
        __syncthreads();
    }
    if (threadIdx.x == 0) atomicAdd(&g_zc, red[0]);
}

// ---------------- K3: S = q k^T * scale + cp_bias ; write cp_bias -----------
__global__ __launch_bounds__(256) void sbias_gemm(float* __restrict__ cp_out,
                                                  const float* __restrict__ p_cps,
                                                  const int* __restrict__ p_flag,
                                                  const int* __restrict__ p_dcmm) {
    __shared__ float As[8][128];
    __shared__ float Bs[8][128];
    __shared__ float zBi[128][KCL];
    __shared__ float zj[128][KCL];
    __shared__ float thi[128];
    __shared__ float thj[128];

    const int t  = threadIdx.x;
    const int tx = t & 15, ty = t >> 4;
    const int n0 = blockIdx.x * 128;
    const int m0 = blockIdx.y * 128;
    const int bh = blockIdx.z;
    const float* qb = g_q + bh * (NTOK * HD);
    const float* kb = g_k + bh * (NTOK * HD);

    if (t < 128) {
        thi[t] = g_th[bh * NTOK + m0 + t];
        thj[t] = g_th[bh * NTOK + n0 + t];
        #pragma unroll
        for (int l = 0; l < KCL; l++) {
            zBi[t][l] = g_zB[(bh * NTOK + m0 + t) * KCL + l];
            zj[t][l]  = g_z [(bh * NTOK + n0 + t) * KCL + l];
        }
    }

    float acc[8][8];
    #pragma unroll
    for (int i = 0; i < 8; i++)
        #pragma unroll
        for (int j = 0; j < 8; j++) acc[i][j] = 0.0f;

    const int lm = t >> 1, lkc = (t & 1) * 4;   // A loader
    const int lj = t >> 1, lh  = (t & 1) * 4;   // B (k, transposed) loader

    for (int kt = 0; kt < HD; kt += 8) {
        float4 av = *(const float4*)&qb[(m0 + lm) * HD + kt + lkc];
        As[lkc + 0][lm] = av.x; As[lkc + 1][lm] = av.y;
        As[lkc + 2][lm] = av.z; As[lkc + 3][lm] = av.w;
        float4 kv = *(const float4*)&kb[(n0 + lj) * HD + kt + lh];
        Bs[lh + 0][lj] = kv.x; Bs[lh + 1][lj] = kv.y;
        Bs[lh + 2][lj] = kv.z; Bs[lh + 3][lj] = kv.w;
        __syncthreads();
        #pragma unroll
        for (int kk = 0; kk < 8; kk++) {
            float4 a0 = *(float4*)&As[kk][ty * 8];
            float4 a1 = *(float4*)&As[kk][ty * 8 + 4];
            float4 b0 = *(float4*)&Bs[kk][tx * 8];
            float4 b1 = *(float4*)&Bs[kk][tx * 8 + 4];
            float a[8] = {a0.x,a0.y,a0.z,a0.w,a1.x,a1.y,a1.z,a1.w};
            float b[8] = {b0.x,b0.y,b0.z,b0.w,b1.x,b1.y,b1.z,b1.w};
            #pragma unroll
            for (int i = 0; i < 8; i++)
                #pragma unroll
                for (int j = 0; j < 8; j++) acc[i][j] += a[i] * b[j];
        }
        __syncthreads();
    }

    const float gate = (p_flag[0] != 0 && p_dcmm[0] != 0) ? 1.0f : 0.0f;
    const float cps = p_cps[0];
    const long long base = (long long)bh * NTOK * NTOK;

    #pragma unroll
    for (int i = 0; i < 8; i++) {
        const int ri = ty * 8 + i;
        #pragma unroll
        for (int j = 0; j < 8; j++) {
            const int cj = tx * 8 + j;
            float bias = 0.0f;
            if (gate != 0.0f) {
                float dot = 0.0f;
                #pragma unroll
                for (int l = 0; l < KCL; l++) dot += zBi[ri][l] * zj[cj][l];
                bias = cps * thi[ri] * thj[cj] * tanhf(dot);
            }
            const long long off = base + (long long)(m0 + ri) * NTOK + (n0 + cj);
            g_S[off] = acc[i][j] * 0.125f + bias;   // scale = 64^-0.5
            cp_out[off] = bias;
        }
    }
}

// ---------------- K4: row softmax over g_S (in place) -----------------------
__global__ __launch_bounds__(256) void softmax_rows() {
    const long long row = blockIdx.x;
    const int t = threadIdx.x;
    float* p = g_S + row * NTOK;
    float4 v = *(float4*)&p[t * 4];
    float m = fmaxf(fmaxf(v.x, v.y), fmaxf(v.z, v.w));
    #pragma unroll
    for (int o = 16; o > 0; o >>= 1) m = fmaxf(m, __shfl_xor_sync(0xffffffffu, m, o));
    __shared__ float red[8];
    const int wid = t >> 5, lane = t & 31;
    if (lane == 0) red[wid] = m;
    __syncthreads();
    float bm = red[0];
    #pragma unroll
    for (int i = 1; i < 8; i++) bm = fmaxf(bm, red[i]);

    float e0 = __expf(v.x - bm), e1 = __expf(v.y - bm);
    float e2 = __expf(v.z - bm), e3 = __expf(v.w - bm);
    float s = e0 + e1 + e2 + e3;
    #pragma unroll
    for (int o = 16; o > 0; o >>= 1) s += __shfl_xor_sync(0xffffffffu, s, o);
    __syncthreads();
    if (lane == 0) red[wid] = s;
    __syncthreads();
    float bs = 0.0f;
    #pragma unroll
    for (int i = 0; i < 8; i++) bs += red[i];
    const float inv = 1.0f / bs;
    v.x = e0 * inv; v.y = e1 * inv; v.z = e2 * inv; v.w = e3 * inv;
    *(float4*)&p[t * 4] = v;
}

// ---------------- K5: O = P @ V  (per bh: 1024x1024 @ 1024x64) --------------
__global__ __launch_bounds__(256) void pv_gemm() {
    __shared__ float Ps[16][64];
    __shared__ float Vs[16][64];
    const int t  = threadIdx.x;
    const int tx = t & 15, ty = t >> 4;
    const int bh = blockIdx.y;
    const int i0 = blockIdx.x * 64;
    const float* Pb = g_S + (long long)bh * NTOK * NTOK;
    const float* Vb = g_v + bh * (NTOK * HD);

    float acc[4][4];
    #pragma unroll
    for (int i = 0; i < 4; i++)
        #pragma unroll
        for (int j = 0; j < 4; j++) acc[i][j] = 0.0f;

    const int pm = t >> 2, pk = (t & 3) * 4;
    const int vk = t >> 4, vc = (t & 15) * 4;

    for (int kt = 0; kt < NTOK; kt += 16) {
        float4 pv4 = *(const float4*)&Pb[(long long)(i0 + pm) * NTOK + kt + pk];
        Ps[pk + 0][pm] = pv4.x; Ps[pk + 1][pm] = pv4.y;
        Ps[pk + 2][pm] = pv4.z; Ps[pk + 3][pm] = pv4.w;
        *(float4*)&Vs[vk][vc] = *(const float4*)&Vb[(kt + vk) * HD + vc];
        __syncthreads();
        #pragma unroll
        for (int kk = 0; kk < 16; kk++) {
            float4 a4 = *(float4*)&Ps[kk][ty * 4];
            float4 b4 = *(float4*)&Vs[kk][tx * 4];
            float a[4] = {a4.x, a4.y, a4.z, a4.w};
            float b[4] = {b4.x, b4.y, b4.z, b4.w};
            #pragma unroll
            for (int i = 0; i < 4; i++)
                #pragma unroll
                for (int j = 0; j < 4; j++) acc[i][j] += a[i] * b[j];
        }
        __syncthreads();
    }
    const int b = bh >> 4, h = bh & 15;
    #pragma unroll
    for (int i = 0; i < 4; i++) {
        const int n = i0 + ty * 4 + i;
        #pragma unroll
        for (int j = 0; j < 4; j++) {
            const int d = tx * 4 + j;
            g_oh[(b * NTOK + n) * CDIM + h * HD + d] = acc[i][j];
        }
    }
}

// ---------------- K6: out = oh @ Wproj + bproj ------------------------------
__global__ __launch_bounds__(256) void proj_gemm(const float* __restrict__ W,
                                                 const float* __restrict__ bias,
                                                 float* __restrict__ out) {
    __shared__ float As[8][128];
    __shared__ float Bs[8][128];
    const int t  = threadIdx.x;
    const int tx = t & 15, ty = t >> 4;
    const int m0 = blockIdx.y * 128;
    const int n0 = blockIdx.x * 128;
    float acc[8][8];
    #pragma unroll
    for (int i = 0; i < 8; i++)
        #pragma unroll
        for (int j = 0; j < 8; j++) acc[i][j] = 0.0f;

    const int lm  = t >> 1, lkc = (t & 1) * 4;
    const int lkk = t >> 5, lc  = (t & 31) * 4;

    for (int kt = 0; kt < 1024; kt += 8) {
        float4 av = *(const float4*)&g_oh[(m0 + lm) * 1024 + kt + lkc];
        As[lkc + 0][lm] = av.x; As[lkc + 1][lm] = av.y;
        As[lkc + 2][lm] = av.z; As[lkc + 3][lm] = av.w;
        *(float4*)&Bs[lkk][lc] = *(const float4*)&W[(kt + lkk) * 1024 + n0 + lc];
        __syncthreads();
        #pragma unroll
        for (int kk = 0; kk < 8; kk++) {
            float4 a0 = *(float4*)&As[kk][ty * 8];
            float4 a1 = *(float4*)&As[kk][ty * 8 + 4];
            float4 b0 = *(float4*)&Bs[kk][tx * 8];
            float4 b1 = *(float4*)&Bs[kk][tx * 8 + 4];
            float a[8] = {a0.x,a0.y,a0.z,a0.w,a1.x,a1.y,a1.z,a1.w};
            float b[8] = {b0.x,b0.y,b0.z,b0.w,b1.x,b1.y,b1.z,b1.w};
            #pragma unroll
            for (int i = 0; i < 8; i++)
                #pragma unroll
                for (int j = 0; j < 8; j++) acc[i][j] += a[i] * b[j];
        }
        __syncthreads();
    }
    #pragma unroll
    for (int i = 0; i < 8; i++) {
        const int m = m0 + ty * 8 + i;
        #pragma unroll
        for (int j = 0; j < 8; j++) {
            const int col = n0 + tx * 8 + j;
            out[m * 1024 + col] = acc[i][j] + bias[col];
        }
    }
}

// ---------------- K7: scalar outputs ----------------------------------------
__global__ void finalize(float* __restrict__ out,
                         const int* __restrict__ p_flag,
                         const int* __restrict__ p_dcmm) {
    if (threadIdx.x == 0) {
        const float gate = (p_flag[0] != 0 && p_dcmm[0] != 0) ? 1.0f : 0.0f;
        out[4194304] = gate * g_zc * (1.0f / 65536.0f);
        out[4194305] = 0.0f;
        out[4194306] = 0.0f;
    }
}

// ---------------------------------------------------------------------------
extern "C" void kernel_launch(void* const* d_in, const int* in_sizes, int n_in,
                              void* d_out, int out_size) {
    const float* x     = (const float*)d_in[0];
    const float* Wqkv  = (const float*)d_in[1];
    const float* Wproj = (const float*)d_in[2];
    const float* bproj = (const float*)d_in[3];
    const float* Wg    = (const float*)d_in[4];
    const float* bg    = (const float*)d_in[5];
    const float* Wt    = (const float*)d_in[6];
    const float* bt    = (const float*)d_in[7];
    const float* affB  = (const float*)d_in[8];
    const float* cps   = (const float*)d_in[9];
    const int*   flag  = (const int*)d_in[10];
    const int*   dcmm  = (const int*)d_in[12];

    float* out = (float*)d_out;
    float* cp  = out + 4194307;   // after out(4194304) + 3 scalars

    zero_zc_kernel<<<1, 1>>>();
    qkv_gemm<<<dim3(24, 32), 256>>>(x, Wqkv);
    zkernel<<<256, 256>>>(Wg, bg, Wt, bt, affB);
    sbias_gemm<<<dim3(8, 8, 64), 256>>>(cp, cps, flag, dcmm);
    softmax_rows<<<65536, 256>>>();
    pv_gemm<<<dim3(16, 64), 256>>>();
    proj_gemm<<<dim3(8, 32), 256>>>(Wproj, bproj, out);
    finalize<<<1, 32>>>(out, flag, dcmm);
}

// round 5
// speedup vs baseline: 1.8819x; 1.8819x over previous
#include <cuda_runtime.h>
#include <cuda_bf16.h>
#include <math.h>
#include <stdint.h>

#define BB 4
#define NTOK 1024
#define CDIM 1024
#define NH 16
#define HD 64
#define KCL 8
#define NBH (BB*NH)
#define NROWS (BB*NH*NTOK)
#define M_ALL (BB*NTOK)

// ---------------- scratch (static device globals) ----------------------------
__device__ float g_q[NROWS*HD];
__device__ float g_k[NROWS*HD];
__device__ float g_v[NROWS*HD];
__device__ float g_S[(long long)NBH*NTOK*NTOK];
__device__ float g_z[NROWS*KCL];
__device__ float g_zB[NROWS*KCL];
__device__ float g_th[NROWS];
__device__ float g_zc;
__device__ __align__(256) __nv_bfloat16 g_xh[M_ALL*CDIM];
__device__ __align__(256) __nv_bfloat16 g_xl[M_ALL*CDIM];
__device__ __align__(256) __nv_bfloat16 g_wqh[3072*1024];
__device__ __align__(256) __nv_bfloat16 g_wql[3072*1024];
__device__ __align__(256) __nv_bfloat16 g_wph[1024*1024];
__device__ __align__(256) __nv_bfloat16 g_wpl[1024*1024];
__device__ __align__(256) __nv_bfloat16 g_ohh[M_ALL*CDIM];
__device__ __align__(256) __nv_bfloat16 g_ohl[M_ALL*CDIM];

// ---------------- helpers ----------------------------------------------------
__device__ __forceinline__ uint32_t smem_u32(const void* p) {
    uint32_t a;
    asm("{ .reg .u64 t; cvta.to.shared.u64 t, %1; cvt.u32.u64 %0, t; }"
        : "=r"(a) : "l"(p));
    return a;
}
__device__ __forceinline__ float fast_tanh(float x) {
    float r;
    asm("tanh.approx.f32 %0, %1;" : "=f"(r) : "f"(x));
    return r;
}
#define CP_ASYNC16(dst, src) \
    asm volatile("cp.async.cg.shared.global [%0], [%1], 16;" :: "r"(dst), "l"(src))
#define CP_COMMIT() asm volatile("cp.async.commit_group;" ::: "memory")
#define CP_WAIT(n)  asm volatile("cp.async.wait_group %0;" :: "n"(n) : "memory")

__device__ __forceinline__ void ldm_x4(uint32_t& r0, uint32_t& r1, uint32_t& r2,
                                       uint32_t& r3, uint32_t addr) {
    asm volatile("ldmatrix.sync.aligned.m8n8.x4.shared.b16 {%0,%1,%2,%3}, [%4];"
                 : "=r"(r0), "=r"(r1), "=r"(r2), "=r"(r3) : "r"(addr));
}
__device__ __forceinline__ void ldm_x2(uint32_t& r0, uint32_t& r1, uint32_t addr) {
    asm volatile("ldmatrix.sync.aligned.m8n8.x2.shared.b16 {%0,%1}, [%2];"
                 : "=r"(r0), "=r"(r1) : "r"(addr));
}
__device__ __forceinline__ void mma_bf16(float* c, const uint32_t* a, const uint32_t* b) {
    asm volatile(
        "mma.sync.aligned.m16n8k16.row.col.f32.bf16.bf16.f32 "
        "{%0,%1,%2,%3}, {%4,%5,%6,%7}, {%8,%9}, {%0,%1,%2,%3};"
        : "+f"(c[0]), "+f"(c[1]), "+f"(c[2]), "+f"(c[3])
        : "r"(a[0]), "r"(a[1]), "r"(a[2]), "r"(a[3]), "r"(b[0]), "r"(b[1]));
}

// ---------------------------------------------------------------------------
__global__ void zero_zc_kernel() { g_zc = 0.0f; }

// ---------------- prep: x -> hi/lo bf16 -------------------------------------
__global__ __launch_bounds__(256) void convert_x(const float* __restrict__ x) {
    int i = (blockIdx.x * 256 + threadIdx.x) * 4;
    float4 v = *(const float4*)&x[i];
    float vals[4] = {v.x, v.y, v.z, v.w};
    __nv_bfloat16 h[4], l[4];
    #pragma unroll
    for (int c = 0; c < 4; c++) {
        h[c] = __float2bfloat16(vals[c]);
        l[c] = __float2bfloat16(vals[c] - __bfloat162float(h[c]));
    }
    *(__nv_bfloat162*)&g_xh[i]     = __nv_bfloat162(h[0], h[1]);
    *(__nv_bfloat162*)&g_xh[i + 2] = __nv_bfloat162(h[2], h[3]);
    *(__nv_bfloat162*)&g_xl[i]     = __nv_bfloat162(l[0], l[1]);
    *(__nv_bfloat162*)&g_xl[i + 2] = __nv_bfloat162(l[2], l[3]);
}

// ---------------- prep: W[K,N] -> transposed hi/lo bf16 [N,K] ----------------
__global__ void transW(const float* __restrict__ W, int N, int which) {
    __shared__ float s[32][33];
    __nv_bfloat16* Th = which ? g_wph : g_wqh;
    __nv_bfloat16* Tl = which ? g_wpl : g_wql;
    const int n0 = blockIdx.x * 32, k0 = blockIdx.y * 32;
    const int tx = threadIdx.x, ty = threadIdx.y;
    #pragma unroll
    for (int i = 0; i < 4; i++)
        s[ty + i * 8][tx] = W[(size_t)(k0 + ty + i * 8) * N + n0 + tx];
    __syncthreads();
    #pragma unroll
    for (int i = 0; i < 4; i++) {
        int n = ty + i * 8;
        float v = s[tx][n];
        __nv_bfloat16 hh = __float2bfloat16(v);
        Th[(size_t)(n0 + n) * 1024 + k0 + tx] = hh;
        Tl[(size_t)(n0 + n) * 1024 + k0 + tx] = __float2bfloat16(v - __bfloat162float(hh));
    }
}

// ---------------- tensor-core bf16x3 GEMM, 128x128x32 tiles ------------------
#define ROWB 80
#define TILE_B (128 * ROWB)
#define STAGE_B (4 * TILE_B)
#define MMA_SMEM (2 * STAGE_B)

__device__ __forceinline__ void ld_stage(uint32_t sb, int stage,
        const __nv_bfloat16* __restrict__ Ah, const __nv_bfloat16* __restrict__ Al,
        const __nv_bfloat16* __restrict__ Bh, const __nv_bfloat16* __restrict__ Bl,
        int m0, int n0, int kc, int t) {
    const int row = t >> 2, chunk = t & 3;
    const uint32_t base = sb + stage * STAGE_B;
    const uint32_t soff = row * ROWB + chunk * 16;
    const size_t goffA = (size_t)(m0 + row) * 1024 + kc + chunk * 8;
    const size_t goffB = (size_t)(n0 + row) * 1024 + kc + chunk * 8;
    #pragma unroll
    for (int i = 0; i < 2; i++) {
        const uint32_t so = soff + i * 64 * ROWB;
        const size_t ga = goffA + (size_t)i * 64 * 1024;
        const size_t gb = goffB + (size_t)i * 64 * 1024;
        CP_ASYNC16(base + 0 * TILE_B + so, Ah + ga);
        CP_ASYNC16(base + 1 * TILE_B + so, Al + ga);
        CP_ASYNC16(base + 2 * TILE_B + so, Bh + gb);
        CP_ASYNC16(base + 3 * TILE_B + so, Bl + gb);
    }
}

__global__ __launch_bounds__(256) void mma_gemm(const float* __restrict__ bias,
                                                float* __restrict__ outp, int mode) {
    extern __shared__ char sm[];
    const uint32_t sb = smem_u32(sm);
    const int t = threadIdx.x, wid = t >> 5, lane = t & 31;
    const int wm = wid >> 2, wn = wid & 3;
    const int n0 = blockIdx.x * 128, m0 = blockIdx.y * 128;

    const __nv_bfloat16* Ah = mode ? g_ohh : g_xh;
    const __nv_bfloat16* Al = mode ? g_ohl : g_xl;
    const __nv_bfloat16* Bh = mode ? g_wph : g_wqh;
    const __nv_bfloat16* Bl = mode ? g_wpl : g_wql;

    float acc[4][4][4];
    #pragma unroll
    for (int mi = 0; mi < 4; mi++)
        #pragma unroll
        for (int ni = 0; ni < 4; ni++)
            #pragma unroll
            for (int r = 0; r < 4; r++) acc[mi][ni][r] = 0.0f;

    const uint32_t a_row = wm * 64 + (lane & 15);
    const uint32_t a_kb  = (lane >> 4) * 16;
    const uint32_t b_row = wn * 32 + (lane & 7);
    const uint32_t b_kb  = ((lane >> 3) & 1) * 16;

    ld_stage(sb, 0, Ah, Al, Bh, Bl, m0, n0, 0, t);
    CP_COMMIT();

    for (int kb = 0; kb < 32; kb++) {
        if (kb + 1 < 32) {
            ld_stage(sb, (kb + 1) & 1, Ah, Al, Bh, Bl, m0, n0, (kb + 1) * 32, t);
            CP_COMMIT();
            CP_WAIT(1);
        } else {
            CP_WAIT(0);
        }
        __syncthreads();

        const uint32_t st = sb + (kb & 1) * STAGE_B;
        #pragma unroll
        for (int ks = 0; ks < 2; ks++) {
            const uint32_t kbyte = ks * 32;
            uint32_t afh[4][4], afl[4][4], bfh[4][2], bfl[4][2];
            #pragma unroll
            for (int mi = 0; mi < 4; mi++) {
                const uint32_t ar = st + (a_row + mi * 16) * ROWB + kbyte + a_kb;
                ldm_x4(afh[mi][0], afh[mi][1], afh[mi][2], afh[mi][3], ar);
                ldm_x4(afl[mi][0], afl[mi][1], afl[mi][2], afl[mi][3], ar + TILE_B);
            }
            #pragma unroll
            for (int ni = 0; ni < 4; ni++) {
                const uint32_t br = st + 2 * TILE_B + (b_row + ni * 8) * ROWB + kbyte + b_kb;
                ldm_x2(bfh[ni][0], bfh[ni][1], br);
                ldm_x2(bfl[ni][0], bfl[ni][1], br + TILE_B);
            }
            #pragma unroll
            for (int mi = 0; mi < 4; mi++)
                #pragma unroll
                for (int ni = 0; ni < 4; ni++) {
                    mma_bf16(acc[mi][ni], afh[mi], bfh[ni]);
                    mma_bf16(acc[mi][ni], afh[mi], bfl[ni]);
                    mma_bf16(acc[mi][ni], afl[mi], bfh[ni]);
                }
        }
        __syncthreads();
    }

    const int er = lane >> 2, ec = (lane & 3) * 2;
    #pragma unroll
    for (int mi = 0; mi < 4; mi++) {
        #pragma unroll
        for (int half = 0; half < 2; half++) {
            const int m = m0 + wm * 64 + mi * 16 + er + half * 8;
            #pragma unroll
            for (int ni = 0; ni < 4; ni++) {
                const float v0 = acc[mi][ni][half * 2];
                const float v1 = acc[mi][ni][half * 2 + 1];
                const int col = n0 + wn * 32 + ni * 8 + ec;
                if (mode == 0) {
                    const int b = m >> 10, n = m & 1023;
                    #pragma unroll
                    for (int u = 0; u < 2; u++) {
                        const int c2 = col + u;
                        const int which = c2 >> 10, rem = c2 & 1023;
                        const int hh = rem >> 6, d = rem & 63;
                        float* dst = (which == 0) ? g_q : (which == 1) ? g_k : g_v;
                        dst[(((b << 4) + hh) * 1024 + n) * 64 + d] = u ? v1 : v0;
                    }
                } else {
                    float2 w = make_float2(v0 + bias[col], v1 + bias[col + 1]);
                    *(float2*)&outp[(size_t)m * 1024 + col] = w;
                }
            }
        }
    }
}

// ---------------- K2: cluster softmax z, zB, theta ---------------------------
__global__ __launch_bounds__(256) void zkernel(const float* __restrict__ Wg,
                                               const float* __restrict__ bg,
                                               const float* __restrict__ Wt,
                                               const float* __restrict__ bt,
                                               const float* __restrict__ affB) {
    const int r = blockIdx.x * 256 + threadIdx.x;
    const int h = (r >> 10) & (NH - 1);
    const float* q = g_q + r * HD;

    float g[KCL];
    #pragma unroll
    for (int l = 0; l < KCL; l++) g[l] = bg[l];
    float th = bt[0];
    for (int k = 0; k < HD; k++) {
        const float qv = q[k];
        th += qv * Wt[k];
        #pragma unroll
        for (int l = 0; l < KCL; l++) g[l] += qv * Wg[k * KCL + l];
    }
    float mx = g[0];
    #pragma unroll
    for (int l = 1; l < KCL; l++) mx = fmaxf(mx, g[l]);
    float s = 0.0f;
    #pragma unroll
    for (int l = 0; l < KCL; l++) { g[l] = __expf(g[l] - mx); s += g[l]; }
    const float inv = 1.0f / s;
    float ent = 0.0f;
    #pragma unroll
    for (int l = 0; l < KCL; l++) {
        const float z = g[l] * inv;
        g[l] = z;
        ent -= z * logf(z + 1e-8f);
    }
    float zB[KCL];
    #pragma unroll
    for (int l = 0; l < KCL; l++) zB[l] = 0.0f;
    #pragma unroll
    for (int k = 0; k < KCL; k++) {
        const float zk = g[k];
        #pragma unroll
        for (int l = 0; l < KCL; l++) {
            const float a = affB[h * 64 + k * KCL + l];
            zB[l] += zk / (1.0f + __expf(-a));
        }
    }
    g_th[r] = fmaxf(th, 0.0f);
    #pragma unroll
    for (int l = 0; l < KCL; l++) { g_z[r * KCL + l] = g[l]; g_zB[r * KCL + l] = zB[l]; }

    __shared__ float red[256];
    red[threadIdx.x] = ent;
    __syncthreads();
    for (int s2 = 128; s2 > 0; s2 >>= 1) {
        if (threadIdx.x < s2) red[threadIdx.x] += red[threadIdx.x + s2];
        __syncthreads();
    }
    if (threadIdx.x == 0) atomicAdd(&g_zc, red[0]);
}

// ---------------- K3: S = q k^T * scale + cp_bias ----------------------------
__global__ __launch_bounds__(256, 2) void sbias_gemm(float* __restrict__ cp_out,
                                                     const float* __restrict__ p_cps,
                                                     const int* __restrict__ p_flag,
                                                     const int* __restrict__ p_dcmm) {
    __shared__ float As[32][132];
    __shared__ float Bs[32][132];
    __shared__ float zBi[128][KCL];
    __shared__ float zj[128][KCL];
    __shared__ float thi[128];
    __shared__ float thj[128];

    const int t  = threadIdx.x;
    const int tx = t & 15, ty = t >> 4;
    const int n0 = blockIdx.x * 128;
    const int m0 = blockIdx.y * 128;
    const int bh = blockIdx.z;
    const float* qb = g_q + bh * (NTOK * HD);
    const float* kb = g_k + bh * (NTOK * HD);

    if (t < 128) {
        thi[t] = g_th[bh * NTOK + m0 + t];
        thj[t] = g_th[bh * NTOK + n0 + t];
        #pragma unroll
        for (int l = 0; l < KCL; l++) {
            zBi[t][l] = g_zB[(bh * NTOK + m0 + t) * KCL + l];
            zj[t][l]  = g_z [(bh * NTOK + n0 + t) * KCL + l];
        }
    }

    float acc[8][8];
    #pragma unroll
    for (int i = 0; i < 8; i++)
        #pragma unroll
        for (int j = 0; j < 8; j++) acc[i][j] = 0.0f;

    for (int kt = 0; kt < HD; kt += 32) {
        #pragma unroll
        for (int i = 0; i < 4; i++) {
            const int u = t + i * 256;
            const int row = u >> 3, seg = u & 7;
            float4 v = *(const float4*)&qb[(m0 + row) * 64 + kt + seg * 4];
            As[seg * 4 + 0][row] = v.x; As[seg * 4 + 1][row] = v.y;
            As[seg * 4 + 2][row] = v.z; As[seg * 4 + 3][row] = v.w;
            float4 w = *(const float4*)&kb[(n0 + row) * 64 + kt + seg * 4];
            Bs[seg * 4 + 0][row] = w.x; Bs[seg * 4 + 1][row] = w.y;
            Bs[seg * 4 + 2][row] = w.z; Bs[seg * 4 + 3][row] = w.w;
        }
        __syncthreads();
        #pragma unroll 8
        for (int kk = 0; kk < 32; kk++) {
            float4 a0 = *(float4*)&As[kk][ty * 8];
            float4 a1 = *(float4*)&As[kk][ty * 8 + 4];
            float4 b0 = *(float4*)&Bs[kk][tx * 8];
            float4 b1 = *(float4*)&Bs[kk][tx * 8 + 4];
            float a[8] = {a0.x,a0.y,a0.z,a0.w,a1.x,a1.y,a1.z,a1.w};
            float b[8] = {b0.x,b0.y,b0.z,b0.w,b1.x,b1.y,b1.z,b1.w};
            #pragma unroll
            for (int i = 0; i < 8; i++)
                #pragma unroll
                for (int j = 0; j < 8; j++) acc[i][j] += a[i] * b[j];
        }
        __syncthreads();
    }

    const float gate = (p_flag[0] != 0 && p_dcmm[0] != 0) ? 1.0f : 0.0f;
    const float cps = p_cps[0] * gate;
    const long long base = (long long)bh * NTOK * NTOK;

    #pragma unroll
    for (int i = 0; i < 8; i++) {
        const int ri = ty * 8 + i;
        float zbr[KCL];
        #pragma unroll
        for (int l = 0; l < KCL; l++) zbr[l] = zBi[ri][l];
        const float fi = cps * thi[ri];
        float sv[8], bv[8];
        #pragma unroll
        for (int j = 0; j < 8; j++) {
            const int cj = tx * 8 + j;
            float dot = 0.0f;
            #pragma unroll
            for (int l = 0; l < KCL; l++) dot += zbr[l] * zj[cj][l];
            const float bias = fi * thj[cj] * fast_tanh(dot);
            bv[j] = bias;
            sv[j] = acc[i][j] * 0.125f + bias;
        }
        const long long off = base + (long long)(m0 + ri) * NTOK + n0 + tx * 8;
        *(float4*)&g_S[off]     = make_float4(sv[0], sv[1], sv[2], sv[3]);
        *(float4*)&g_S[off + 4] = make_float4(sv[4], sv[5], sv[6], sv[7]);
        // cp_out is 12 bytes off 16B alignment (out + 4194307) -> scalar stores only
        #pragma unroll
        for (int j = 0; j < 8; j++) cp_out[off + j] = bv[j];
    }
}

// ---------------- K4: row softmax over g_S (in place) ------------------------
__global__ __launch_bounds__(256) void softmax_rows() {
    const long long row = blockIdx.x;
    const int t = threadIdx.x;
    float* p = g_S + row * NTOK;
    float4 v = *(float4*)&p[t * 4];
    float m = fmaxf(fmaxf(v.x, v.y), fmaxf(v.z, v.w));
    #pragma unroll
    for (int o = 16; o > 0; o >>= 1) m = fmaxf(m, __shfl_xor_sync(0xffffffffu, m, o));
    __shared__ float red[8];
    const int wid = t >> 5, lane = t & 31;
    if (lane == 0) red[wid] = m;
    __syncthreads();
    float bm = red[0];
    #pragma unroll
    for (int i = 1; i < 8; i++) bm = fmaxf(bm, red[i]);

    float e0 = __expf(v.x - bm), e1 = __expf(v.y - bm);
    float e2 = __expf(v.z - bm), e3 = __expf(v.w - bm);
    float s = e0 + e1 + e2 + e3;
    #pragma unroll
    for (int o = 16; o > 0; o >>= 1) s += __shfl_xor_sync(0xffffffffu, s, o);
    __syncthreads();
    if (lane == 0) red[wid] = s;
    __syncthreads();
    float bs = 0.0f;
    #pragma unroll
    for (int i = 0; i < 8; i++) bs += red[i];
    const float inv = 1.0f / bs;
    v.x = e0 * inv; v.y = e1 * inv; v.z = e2 * inv; v.w = e3 * inv;
    *(float4*)&p[t * 4] = v;
}

// ---------------- K5: O = P @ V, epilogue -> hi/lo bf16 ----------------------
__global__ __launch_bounds__(256) void pv_gemm() {
    __shared__ float Ps[32][132];
    __shared__ float Vs[32][68];
    const int t  = threadIdx.x;
    const int tx = t & 15, ty = t >> 4;
    const int bh = blockIdx.y;
    const int i0 = blockIdx.x * 128;
    const float* Pb = g_S + (long long)bh * NTOK * NTOK;
    const float* Vb = g_v + bh * (NTOK * HD);

    float acc[8][4];
    #pragma unroll
    for (int i = 0; i < 8; i++)
        #pragma unroll
        for (int j = 0; j < 4; j++) acc[i][j] = 0.0f;

    for (int kt = 0; kt < NTOK; kt += 32) {
        #pragma unroll
        for (int i = 0; i < 4; i++) {
            const int u = t + i * 256;
            const int row = u >> 3, seg = u & 7;
            float4 v = *(const float4*)&Pb[(long long)(i0 + row) * NTOK + kt + seg * 4];
            Ps[seg * 4 + 0][row] = v.x; Ps[seg * 4 + 1][row] = v.y;
            Ps[seg * 4 + 2][row] = v.z; Ps[seg * 4 + 3][row] = v.w;
        }
        #pragma unroll
        for (int i = 0; i < 2; i++) {
            const int u = t + i * 256;
            const int vk = u >> 4, vc = (u & 15) * 4;
            *(float4*)&Vs[vk][vc] = *(const float4*)&Vb[(kt + vk) * HD + vc];
        }
        __syncthreads();
        #pragma unroll 8
        for (int kk = 0; kk < 32; kk++) {
            float4 a0 = *(float4*)&Ps[kk][ty * 8];
            float4 a1 = *(float4*)&Ps[kk][ty * 8 + 4];
            float4 b4 = *(float4*)&Vs[kk][tx * 4];
            float a[8] = {a0.x,a0.y,a0.z,a0.w,a1.x,a1.y,a1.z,a1.w};
            float b[4] = {b4.x,b4.y,b4.z,b4.w};
            #pragma unroll
            for (int i = 0; i < 8; i++)
                #pragma unroll
                for (int j = 0; j < 4; j++) acc[i][j] += a[i] * b[j];
        }
        __syncthreads();
    }
    const int b = bh >> 4, hh = bh & 15;
    #pragma unroll
    for (int i = 0; i < 8; i++) {
        const int n = i0 + ty * 8 + i;
        const size_t ro = (size_t)(b * NTOK + n) * CDIM + hh * HD + tx * 4;
        #pragma unroll
        for (int j = 0; j < 4; j++) {
            const float v = acc[i][j];
            __nv_bfloat16 hb = __float2bfloat16(v);
            g_ohh[ro + j] = hb;
            g_ohl[ro + j] = __float2bfloat16(v - __bfloat162float(hb));
        }
    }
}

// ---------------- K7: scalar outputs -----------------------------------------
__global__ void finalize(float* __restrict__ out,
                         const int* __restrict__ p_flag,
                         const int* __restrict__ p_dcmm) {
    if (threadIdx.x == 0) {
        const float gate = (p_flag[0] != 0 && p_dcmm[0] != 0) ? 1.0f : 0.0f;
        out[4194304] = gate * g_zc * (1.0f / 65536.0f);
        out[4194305] = 0.0f;
        out[4194306] = 0.0f;
    }
}

// ---------------------------------------------------------------------------
extern "C" void kernel_launch(void* const* d_in, const int* in_sizes, int n_in,
                              void* d_out, int out_size) {
    const float* x     = (const float*)d_in[0];
    const float* Wqkv  = (const float*)d_in[1];
    const float* Wproj = (const float*)d_in[2];
    const float* bproj = (const float*)d_in[3];
    const float* Wg    = (const float*)d_in[4];
    const float* bg    = (const float*)d_in[5];
    const float* Wt    = (const float*)d_in[6];
    const float* bt    = (const float*)d_in[7];
    const float* affB  = (const float*)d_in[8];
    const float* cps   = (const float*)d_in[9];
    const int*   flag  = (const int*)d_in[10];
    const int*   dcmm  = (const int*)d_in[12];

    float* out = (float*)d_out;
    float* cp  = out + 4194307;

    cudaFuncSetAttribute(mma_gemm, cudaFuncAttributeMaxDynamicSharedMemorySize, MMA_SMEM);

    zero_zc_kernel<<<1, 1>>>();
    convert_x<<<4096, 256>>>(x);
    transW<<<dim3(96, 32), dim3(32, 8)>>>(Wqkv, 3072, 0);
    transW<<<dim3(32, 32), dim3(32, 8)>>>(Wproj, 1024, 1);
    mma_gemm<<<dim3(24, 32), 256, MMA_SMEM>>>(nullptr, nullptr, 0);
    zkernel<<<256, 256>>>(Wg, bg, Wt, bt, affB);
    sbias_gemm<<<dim3(8, 8, 64), 256>>>(cp, cps, flag, dcmm);
    softmax_rows<<<65536, 256>>>();
    pv_gemm<<<dim3(8, 64), 256>>>();
    mma_gemm<<<dim3(8, 32), 256, MMA_SMEM>>>(bproj, out, 1);
    finalize<<<1, 32>>>(out, flag, dcmm);
}

// round 6
// speedup vs baseline: 2.3949x; 1.2726x over previous
#include <cuda_runtime.h>
#include <cuda_bf16.h>
#include <math.h>
#include <stdint.h>

#define BB 4
#define NTOK 1024
#define CDIM 1024
#define NH 16
#define HD 64
#define KCL 8
#define NBH (BB*NH)
#define NROWS (BB*NH*NTOK)
#define M_ALL (BB*NTOK)

// ---------------- scratch (static device globals) ----------------------------
__device__ float g_q[NROWS*HD];
__device__ float g_S[(long long)NBH*NTOK*NTOK];
__device__ float g_z[NROWS*KCL];
__device__ float g_zB[NROWS*KCL];
__device__ float g_th[NROWS];
__device__ float g_zc;
__device__ __align__(256) __nv_bfloat16 g_xh[M_ALL*CDIM];
__device__ __align__(256) __nv_bfloat16 g_xl[M_ALL*CDIM];
__device__ __align__(256) __nv_bfloat16 g_wqh[3072*1024];
__device__ __align__(256) __nv_bfloat16 g_wql[3072*1024];
__device__ __align__(256) __nv_bfloat16 g_wph[1024*1024];
__device__ __align__(256) __nv_bfloat16 g_wpl[1024*1024];
__device__ __align__(256) __nv_bfloat16 g_ohh[M_ALL*CDIM];
__device__ __align__(256) __nv_bfloat16 g_ohl[M_ALL*CDIM];
__device__ __align__(256) __nv_bfloat16 g_qh[NROWS*HD], g_ql[NROWS*HD];
__device__ __align__(256) __nv_bfloat16 g_kh[NROWS*HD], g_kl[NROWS*HD];
__device__ __align__(256) __nv_bfloat16 g_vh[NROWS*HD], g_vl[NROWS*HD];
__device__ __align__(256) __nv_bfloat16 g_vth[NROWS*HD], g_vtl[NROWS*HD];
__device__ __align__(256) __nv_bfloat16 g_Ph[(long long)NBH*NTOK*NTOK];
__device__ __align__(256) __nv_bfloat16 g_Pl[(long long)NBH*NTOK*NTOK];

// ---------------- helpers ----------------------------------------------------
__device__ __forceinline__ uint32_t smem_u32(const void* p) {
    uint32_t a;
    asm("{ .reg .u64 t; cvta.to.shared.u64 t, %1; cvt.u32.u64 %0, t; }"
        : "=r"(a) : "l"(p));
    return a;
}
__device__ __forceinline__ float fast_tanh(float x) {
    float r;
    asm("tanh.approx.f32 %0, %1;" : "=f"(r) : "f"(x));
    return r;
}
#define CP_ASYNC16(dst, src) \
    asm volatile("cp.async.cg.shared.global [%0], [%1], 16;" :: "r"(dst), "l"(src))
#define CP_COMMIT() asm volatile("cp.async.commit_group;" ::: "memory")
#define CP_WAIT(n)  asm volatile("cp.async.wait_group %0;" :: "n"(n) : "memory")

__device__ __forceinline__ void ldm_x4(uint32_t& r0, uint32_t& r1, uint32_t& r2,
                                       uint32_t& r3, uint32_t addr) {
    asm volatile("ldmatrix.sync.aligned.m8n8.x4.shared.b16 {%0,%1,%2,%3}, [%4];"
                 : "=r"(r0), "=r"(r1), "=r"(r2), "=r"(r3) : "r"(addr));
}
__device__ __forceinline__ void ldm_x2(uint32_t& r0, uint32_t& r1, uint32_t addr) {
    asm volatile("ldmatrix.sync.aligned.m8n8.x2.shared.b16 {%0,%1}, [%2];"
                 : "=r"(r0), "=r"(r1) : "r"(addr));
}
__device__ __forceinline__ void mma_bf16(float* c, const uint32_t* a, const uint32_t* b) {
    asm volatile(
        "mma.sync.aligned.m16n8k16.row.col.f32.bf16.bf16.f32 "
        "{%0,%1,%2,%3}, {%4,%5,%6,%7}, {%8,%9}, {%0,%1,%2,%3};"
        : "+f"(c[0]), "+f"(c[1]), "+f"(c[2]), "+f"(c[3])
        : "r"(a[0]), "r"(a[1]), "r"(a[2]), "r"(a[3]), "r"(b[0]), "r"(b[1]));
}
__device__ __forceinline__ void split_bf16(float v, __nv_bfloat16& hi, __nv_bfloat16& lo) {
    hi = __float2bfloat16(v);
    lo = __float2bfloat16(v - __bfloat162float(hi));
}

// ---------------------------------------------------------------------------
__global__ void zero_zc_kernel() { g_zc = 0.0f; }

// ---------------- prep: x -> hi/lo bf16 -------------------------------------
__global__ __launch_bounds__(256) void convert_x(const float* __restrict__ x) {
    int i = (blockIdx.x * 256 + threadIdx.x) * 4;
    float4 v = *(const float4*)&x[i];
    float vals[4] = {v.x, v.y, v.z, v.w};
    __nv_bfloat16 h[4], l[4];
    #pragma unroll
    for (int c = 0; c < 4; c++) split_bf16(vals[c], h[c], l[c]);
    *(__nv_bfloat162*)&g_xh[i]     = __nv_bfloat162(h[0], h[1]);
    *(__nv_bfloat162*)&g_xh[i + 2] = __nv_bfloat162(h[2], h[3]);
    *(__nv_bfloat162*)&g_xl[i]     = __nv_bfloat162(l[0], l[1]);
    *(__nv_bfloat162*)&g_xl[i + 2] = __nv_bfloat162(l[2], l[3]);
}

// ---------------- prep: W[K,N] -> transposed hi/lo bf16 [N,K] ----------------
__global__ void transW(const float* __restrict__ W, int N, int which) {
    __shared__ float s[32][33];
    __nv_bfloat16* Th = which ? g_wph : g_wqh;
    __nv_bfloat16* Tl = which ? g_wpl : g_wql;
    const int n0 = blockIdx.x * 32, k0 = blockIdx.y * 32;
    const int tx = threadIdx.x, ty = threadIdx.y;
    #pragma unroll
    for (int i = 0; i < 4; i++)
        s[ty + i * 8][tx] = W[(size_t)(k0 + ty + i * 8) * N + n0 + tx];
    __syncthreads();
    #pragma unroll
    for (int i = 0; i < 4; i++) {
        int n = ty + i * 8;
        float v = s[tx][n];
        __nv_bfloat16 hh, ll;
        split_bf16(v, hh, ll);
        Th[(size_t)(n0 + n) * 1024 + k0 + tx] = hh;
        Tl[(size_t)(n0 + n) * 1024 + k0 + tx] = ll;
    }
}

// ---------------- tensor-core bf16x3 GEMM, 128x128x32 tiles ------------------
#define ROWB 80
#define TILE_B (128 * ROWB)
#define STAGE_B (4 * TILE_B)
#define MMA_SMEM (2 * STAGE_B)

__device__ __forceinline__ void ld_stage(uint32_t sb, int stage,
        const __nv_bfloat16* __restrict__ Ah, const __nv_bfloat16* __restrict__ Al,
        const __nv_bfloat16* __restrict__ Bh, const __nv_bfloat16* __restrict__ Bl,
        int m0, int n0, int kc, int t) {
    const int row = t >> 2, chunk = t & 3;
    const uint32_t base = sb + stage * STAGE_B;
    const uint32_t soff = row * ROWB + chunk * 16;
    const size_t goffA = (size_t)(m0 + row) * 1024 + kc + chunk * 8;
    const size_t goffB = (size_t)(n0 + row) * 1024 + kc + chunk * 8;
    #pragma unroll
    for (int i = 0; i < 2; i++) {
        const uint32_t so = soff + i * 64 * ROWB;
        const size_t ga = goffA + (size_t)i * 64 * 1024;
        const size_t gb = goffB + (size_t)i * 64 * 1024;
        CP_ASYNC16(base + 0 * TILE_B + so, Ah + ga);
        CP_ASYNC16(base + 1 * TILE_B + so, Al + ga);
        CP_ASYNC16(base + 2 * TILE_B + so, Bh + gb);
        CP_ASYNC16(base + 3 * TILE_B + so, Bl + gb);
    }
}

__global__ __launch_bounds__(256) void mma_gemm(const float* __restrict__ bias,
                                                float* __restrict__ outp, int mode) {
    extern __shared__ char sm[];
    const uint32_t sb = smem_u32(sm);
    const int t = threadIdx.x, wid = t >> 5, lane = t & 31;
    const int wm = wid >> 2, wn = wid & 3;
    const int n0 = blockIdx.x * 128, m0 = blockIdx.y * 128;

    const __nv_bfloat16* Ah = mode ? g_ohh : g_xh;
    const __nv_bfloat16* Al = mode ? g_ohl : g_xl;
    const __nv_bfloat16* Bh = mode ? g_wph : g_wqh;
    const __nv_bfloat16* Bl = mode ? g_wpl : g_wql;

    float acc[4][4][4];
    #pragma unroll
    for (int mi = 0; mi < 4; mi++)
        #pragma unroll
        for (int ni = 0; ni < 4; ni++)
            #pragma unroll
            for (int r = 0; r < 4; r++) acc[mi][ni][r] = 0.0f;

    const uint32_t a_row = wm * 64 + (lane & 15);
    const uint32_t a_kb  = (lane >> 4) * 16;
    const uint32_t b_row = wn * 32 + (lane & 7);
    const uint32_t b_kb  = ((lane >> 3) & 1) * 16;

    ld_stage(sb, 0, Ah, Al, Bh, Bl, m0, n0, 0, t);
    CP_COMMIT();

    for (int kb = 0; kb < 32; kb++) {
        if (kb + 1 < 32) {
            ld_stage(sb, (kb + 1) & 1, Ah, Al, Bh, Bl, m0, n0, (kb + 1) * 32, t);
            CP_COMMIT();
            CP_WAIT(1);
        } else {
            CP_WAIT(0);
        }
        __syncthreads();

        const uint32_t st = sb + (kb & 1) * STAGE_B;
        #pragma unroll
        for (int ks = 0; ks < 2; ks++) {
            const uint32_t kbyte = ks * 32;
            uint32_t afh[4][4], afl[4][4], bfh[4][2], bfl[4][2];
            #pragma unroll
            for (int mi = 0; mi < 4; mi++) {
                const uint32_t ar = st + (a_row + mi * 16) * ROWB + kbyte + a_kb;
                ldm_x4(afh[mi][0], afh[mi][1], afh[mi][2], afh[mi][3], ar);
                ldm_x4(afl[mi][0], afl[mi][1], afl[mi][2], afl[mi][3], ar + TILE_B);
            }
            #pragma unroll
            for (int ni = 0; ni < 4; ni++) {
                const uint32_t br = st + 2 * TILE_B + (b_row + ni * 8) * ROWB + kbyte + b_kb;
                ldm_x2(bfh[ni][0], bfh[ni][1], br);
                ldm_x2(bfl[ni][0], bfl[ni][1], br + TILE_B);
            }
            #pragma unroll
            for (int mi = 0; mi < 4; mi++)
                #pragma unroll
                for (int ni = 0; ni < 4; ni++) {
                    mma_bf16(acc[mi][ni], afh[mi], bfh[ni]);
                    mma_bf16(acc[mi][ni], afh[mi], bfl[ni]);
                    mma_bf16(acc[mi][ni], afl[mi], bfh[ni]);
                }
        }
        __syncthreads();
    }

    const int er = lane >> 2, ec = (lane & 3) * 2;
    #pragma unroll
    for (int mi = 0; mi < 4; mi++) {
        #pragma unroll
        for (int half = 0; half < 2; half++) {
            const int m = m0 + wm * 64 + mi * 16 + er + half * 8;
            #pragma unroll
            for (int ni = 0; ni < 4; ni++) {
                const float v0 = acc[mi][ni][half * 2];
                const float v1 = acc[mi][ni][half * 2 + 1];
                const int col = n0 + wn * 32 + ni * 8 + ec;
                if (mode == 0) {
                    const int b = m >> 10, n = m & 1023;
                    #pragma unroll
                    for (int u = 0; u < 2; u++) {
                        const int c2 = col + u;
                        const int which = c2 >> 10, rem = c2 & 1023;
                        const int hh = rem >> 6, d = rem & 63;
                        const float val = u ? v1 : v0;
                        const size_t idx = (size_t)(((b << 4) + hh) * 1024 + n) * 64 + d;
                        __nv_bfloat16 bhi, blo;
                        split_bf16(val, bhi, blo);
                        if (which == 0) {
                            g_q[idx] = val; g_qh[idx] = bhi; g_ql[idx] = blo;
                        } else if (which == 1) {
                            g_kh[idx] = bhi; g_kl[idx] = blo;
                        } else {
                            g_vh[idx] = bhi; g_vl[idx] = blo;
                        }
                    }
                } else {
                    float2 w = make_float2(v0 + bias[col], v1 + bias[col + 1]);
                    *(float2*)&outp[(size_t)m * 1024 + col] = w;
                }
            }
        }
    }
}

// ---------------- V transpose: [bh][m][d] -> [bh][d][m] ----------------------
__global__ __launch_bounds__(256) void vtrans() {
    __shared__ __nv_bfloat16 s[32][72];
    const int bh = blockIdx.y, m0 = blockIdx.x * 32;
    const int t = threadIdx.x;
    #pragma unroll
    for (int which = 0; which < 2; which++) {
        const __nv_bfloat16* src = which ? g_vl : g_vh;
        __nv_bfloat16* dst = which ? g_vtl : g_vth;
        const int row = t >> 3, c = (t & 7) * 8;
        *(uint4*)&s[row][c] =
            *(const uint4*)&src[((size_t)bh * 1024 + m0 + row) * 64 + c];
        __syncthreads();
        const int d = t >> 2, ms = (t & 3) * 8;
        __nv_bfloat16 tmp[8];
        #pragma unroll
        for (int i = 0; i < 8; i++) tmp[i] = s[ms + i][d];
        *(uint4*)&dst[((size_t)bh * 64 + d) * 1024 + m0 + ms] = *(uint4*)tmp;
        __syncthreads();
    }
}

// ---------------- K2: cluster softmax z, zB, theta ---------------------------
__global__ __launch_bounds__(256) void zkernel(const float* __restrict__ Wg,
                                               const float* __restrict__ bg,
                                               const float* __restrict__ Wt,
                                               const float* __restrict__ bt,
                                               const float* __restrict__ affB) {
    const int r = blockIdx.x * 256 + threadIdx.x;
    const int h = (r >> 10) & (NH - 1);
    const float* q = g_q + r * HD;

    float g[KCL];
    #pragma unroll
    for (int l = 0; l < KCL; l++) g[l] = bg[l];
    float th = bt[0];
    for (int k = 0; k < HD; k++) {
        const float qv = q[k];
        th += qv * Wt[k];
        #pragma unroll
        for (int l = 0; l < KCL; l++) g[l] += qv * Wg[k * KCL + l];
    }
    float mx = g[0];
    #pragma unroll
    for (int l = 1; l < KCL; l++) mx = fmaxf(mx, g[l]);
    float s = 0.0f;
    #pragma unroll
    for (int l = 0; l < KCL; l++) { g[l] = __expf(g[l] - mx); s += g[l]; }
    const float inv = 1.0f / s;
    float ent = 0.0f;
    #pragma unroll
    for (int l = 0; l < KCL; l++) {
        const float z = g[l] * inv;
        g[l] = z;
        ent -= z * logf(z + 1e-8f);
    }
    float zB[KCL];
    #pragma unroll
    for (int l = 0; l < KCL; l++) zB[l] = 0.0f;
    #pragma unroll
    for (int k = 0; k < KCL; k++) {
        const float zk = g[k];
        #pragma unroll
        for (int l = 0; l < KCL; l++) {
            const float a = affB[h * 64 + k * KCL + l];
            zB[l] += zk / (1.0f + __expf(-a));
        }
    }
    g_th[r] = fmaxf(th, 0.0f);
    #pragma unroll
    for (int l = 0; l < KCL; l++) { g_z[r * KCL + l] = g[l]; g_zB[r * KCL + l] = zB[l]; }

    __shared__ float red[256];
    red[threadIdx.x] = ent;
    __syncthreads();
    for (int s2 = 128; s2 > 0; s2 >>= 1) {
        if (threadIdx.x < s2) red[threadIdx.x] += red[threadIdx.x + s2];
        __syncthreads();
    }
    if (threadIdx.x == 0) atomicAdd(&g_zc, red[0]);
}

// ---------------- K3: S = q k^T * scale + cp_bias (HMMA) ---------------------
// smem: Qh 0, Ql 18432, Kh 36864, Kl 55296, zBi 73728, zj 77824, thi 81920, thj 82432
#define QK_ROWB 144
#define QK_TILE (128 * QK_ROWB)
#define QK_SMEM (4 * QK_TILE + 4096 + 4096 + 512 + 512)

__global__ __launch_bounds__(256) void sbias_qk(float* __restrict__ cp_out,
                                                const float* __restrict__ p_cps,
                                                const int* __restrict__ p_flag,
                                                const int* __restrict__ p_dcmm) {
    extern __shared__ char sm[];
    const uint32_t sb = smem_u32(sm);
    float* zBi = (float*)(sm + 4 * QK_TILE);
    float* zjs = (float*)(sm + 4 * QK_TILE + 4096);
    float* thi = (float*)(sm + 4 * QK_TILE + 8192);
    float* thj = (float*)(sm + 4 * QK_TILE + 8704);
    const int t = threadIdx.x, wid = t >> 5, lane = t & 31;
    const int wm = wid >> 2, wn = wid & 3;
    const int n0 = blockIdx.x * 128, m0 = blockIdx.y * 128;
    const int bh = blockIdx.z;

    if (t < 128) {
        thi[t] = g_th[bh * NTOK + m0 + t];
        thj[t] = g_th[bh * NTOK + n0 + t];
        #pragma unroll
        for (int l = 0; l < KCL; l++) {
            zBi[t * KCL + l] = g_zB[(bh * NTOK + m0 + t) * KCL + l];
            zjs[t * KCL + l] = g_z [(bh * NTOK + n0 + t) * KCL + l];
        }
    }
    {
        const size_t qbase = (size_t)(bh * NTOK + m0) * 64;
        const size_t kbase = (size_t)(bh * NTOK + n0) * 64;
        #pragma unroll
        for (int i = 0; i < 4; i++) {
            const int u = t + i * 256;
            const int row = u >> 3, c = u & 7;
            const uint32_t so = row * QK_ROWB + c * 16;
            const size_t gq = qbase + row * 64 + c * 8;
            const size_t gk = kbase + row * 64 + c * 8;
            *(uint4*)(sm + so)                = *(const uint4*)(g_qh + gq);
            *(uint4*)(sm + QK_TILE + so)      = *(const uint4*)(g_ql + gq);
            *(uint4*)(sm + 2 * QK_TILE + so)  = *(const uint4*)(g_kh + gk);
            *(uint4*)(sm + 3 * QK_TILE + so)  = *(const uint4*)(g_kl + gk);
        }
    }
    __syncthreads();

    float acc[4][4][4];
    #pragma unroll
    for (int mi = 0; mi < 4; mi++)
        #pragma unroll
        for (int ni = 0; ni < 4; ni++)
            #pragma unroll
            for (int r = 0; r < 4; r++) acc[mi][ni][r] = 0.0f;

    const uint32_t a_row = wm * 64 + (lane & 15);
    const uint32_t a_kb  = (lane >> 4) * 16;
    const uint32_t b_row = wn * 32 + (lane & 7);
    const uint32_t b_kb  = ((lane >> 3) & 1) * 16;

    #pragma unroll
    for (int ks = 0; ks < 4; ks++) {
        const uint32_t kbyte = ks * 32;
        uint32_t aqh[4][4], aql[4][4], bkh[4][2], bkl[4][2];
        #pragma unroll
        for (int mi = 0; mi < 4; mi++) {
            const uint32_t ar = sb + (a_row + mi * 16) * QK_ROWB + kbyte + a_kb;
            ldm_x4(aqh[mi][0], aqh[mi][1], aqh[mi][2], aqh[mi][3], ar);
            ldm_x4(aql[mi][0], aql[mi][1], aql[mi][2], aql[mi][3], ar + QK_TILE);
        }
        #pragma unroll
        for (int ni = 0; ni < 4; ni++) {
            const uint32_t br = sb + 2 * QK_TILE + (b_row + ni * 8) * QK_ROWB + kbyte + b_kb;
            ldm_x2(bkh[ni][0], bkh[ni][1], br);
            ldm_x2(bkl[ni][0], bkl[ni][1], br + QK_TILE);
        }
        #pragma unroll
        for (int mi = 0; mi < 4; mi++)
            #pragma unroll
            for (int ni = 0; ni < 4; ni++) {
                mma_bf16(acc[mi][ni], aqh[mi], bkh[ni]);
                mma_bf16(acc[mi][ni], aqh[mi], bkl[ni]);
                mma_bf16(acc[mi][ni], aql[mi], bkh[ni]);
            }
    }

    const float gate = (p_flag[0] != 0 && p_dcmm[0] != 0) ? 1.0f : 0.0f;
    const float cps = p_cps[0] * gate;
    const long long base = (long long)bh * NTOK * NTOK;
    const int er = lane >> 2, ec = (lane & 3) * 2;

    #pragma unroll
    for (int mi = 0; mi < 4; mi++) {
        #pragma unroll
        for (int half = 0; half < 2; half++) {
            const int row = wm * 64 + mi * 16 + er + half * 8;
            const float fi = cps * thi[row];
            const float* zbr = &zBi[row * KCL];
            #pragma unroll
            for (int ni = 0; ni < 4; ni++) {
                const int col = wn * 32 + ni * 8 + ec;
                const float v0 = acc[mi][ni][half * 2]     * 0.125f;
                const float v1 = acc[mi][ni][half * 2 + 1] * 0.125f;
                float d0 = 0.0f, d1 = 0.0f;
                #pragma unroll
                for (int l = 0; l < KCL; l++) {
                    d0 += zbr[l] * zjs[col * KCL + l];
                    d1 += zbr[l] * zjs[(col + 1) * KCL + l];
                }
                const float b0 = fi * thj[col]     * fast_tanh(d0);
                const float b1 = fi * thj[col + 1] * fast_tanh(d1);
                const long long off = base + (long long)(m0 + row) * NTOK + n0 + col;
                *(float2*)&g_S[off] = make_float2(v0 + b0, v1 + b1);
                cp_out[off]     = b0;   // cp base is 12B off 16B alignment: scalar only
                cp_out[off + 1] = b1;
            }
        }
    }
}

// ---------------- K4: row softmax, write P hi/lo bf16 ------------------------
__global__ __launch_bounds__(256) void softmax_rows() {
    const long long row = blockIdx.x;
    const int t = threadIdx.x;
    const float* p = g_S + row * NTOK;
    float4 v = *(const float4*)&p[t * 4];
    float m = fmaxf(fmaxf(v.x, v.y), fmaxf(v.z, v.w));
    #pragma unroll
    for (int o = 16; o > 0; o >>= 1) m = fmaxf(m, __shfl_xor_sync(0xffffffffu, m, o));
    __shared__ float red[8];
    const int wid = t >> 5, lane = t & 31;
    if (lane == 0) red[wid] = m;
    __syncthreads();
    float bm = red[0];
    #pragma unroll
    for (int i = 1; i < 8; i++) bm = fmaxf(bm, red[i]);

    float e0 = __expf(v.x - bm), e1 = __expf(v.y - bm);
    float e2 = __expf(v.z - bm), e3 = __expf(v.w - bm);
    float s = e0 + e1 + e2 + e3;
    #pragma unroll
    for (int o = 16; o > 0; o >>= 1) s += __shfl_xor_sync(0xffffffffu, s, o);
    __syncthreads();
    if (lane == 0) red[wid] = s;
    __syncthreads();
    float bs = 0.0f;
    #pragma unroll
    for (int i = 0; i < 8; i++) bs += red[i];
    const float inv = 1.0f / bs;
    float r4[4] = {e0 * inv, e1 * inv, e2 * inv, e3 * inv};
    __nv_bfloat16 hh[4], ll[4];
    #pragma unroll
    for (int i = 0; i < 4; i++) split_bf16(r4[i], hh[i], ll[i]);
    const long long idx = row * NTOK + t * 4;
    *(__nv_bfloat162*)&g_Ph[idx]     = __nv_bfloat162(hh[0], hh[1]);
    *(__nv_bfloat162*)&g_Ph[idx + 2] = __nv_bfloat162(hh[2], hh[3]);
    *(__nv_bfloat162*)&g_Pl[idx]     = __nv_bfloat162(ll[0], ll[1]);
    *(__nv_bfloat162*)&g_Pl[idx + 2] = __nv_bfloat162(ll[2], ll[3]);
}

// ---------------- K5: O = P @ V (HMMA), epilogue -> hi/lo bf16 ---------------
#define PV_ROWB 80
#define PV_A (128 * PV_ROWB)
#define PV_B (64 * PV_ROWB)
#define PV_STAGE (2 * PV_A + 2 * PV_B)
#define PV_SMEM (2 * PV_STAGE)

__device__ __forceinline__ void pv_ld_stage(uint32_t sb, int stage, int bh,
                                            int i0, int kc, int t) {
    const uint32_t base = sb + stage * PV_STAGE;
    #pragma unroll
    for (int i = 0; i < 2; i++) {
        const int u = t + i * 256;
        const int row = u >> 2, c = u & 3;
        const size_t g = ((size_t)bh * 1024 + i0 + row) * 1024 + kc + c * 8;
        const uint32_t so = base + row * PV_ROWB + c * 16;
        CP_ASYNC16(so, g_Ph + g);
        CP_ASYNC16(so + PV_A, g_Pl + g);
    }
    {
        const int row = t >> 2, c = t & 3;
        const size_t g = ((size_t)bh * 64 + row) * 1024 + kc + c * 8;
        const uint32_t so = base + 2 * PV_A + row * PV_ROWB + c * 16;
        CP_ASYNC16(so, g_vth + g);
        CP_ASYNC16(so + PV_B, g_vtl + g);
    }
}

__global__ __launch_bounds__(256, 2) void pv_mma() {
    extern __shared__ char sm[];
    const uint32_t sb = smem_u32(sm);
    const int t = threadIdx.x, wid = t >> 5, lane = t & 31;
    const int wm = wid >> 1, wn = wid & 1;
    const int i0 = blockIdx.x * 128, bh = blockIdx.y;

    float acc[2][4][4];
    #pragma unroll
    for (int mi = 0; mi < 2; mi++)
        #pragma unroll
        for (int ni = 0; ni < 4; ni++)
            #pragma unroll
            for (int r = 0; r < 4; r++) acc[mi][ni][r] = 0.0f;

    const uint32_t a_row = wm * 32 + (lane & 15);
    const uint32_t a_kb  = (lane >> 4) * 16;
    const uint32_t b_row = wn * 32 + (lane & 7);
    const uint32_t b_kb  = ((lane >> 3) & 1) * 16;

    pv_ld_stage(sb, 0, bh, i0, 0, t);
    CP_COMMIT();

    for (int kb = 0; kb < 32; kb++) {
        if (kb + 1 < 32) {
            pv_ld_stage(sb, (kb + 1) & 1, bh, i0, (kb + 1) * 32, t);
            CP_COMMIT();
            CP_WAIT(1);
        } else {
            CP_WAIT(0);
        }
        __syncthreads();

        const uint32_t st = sb + (kb & 1) * PV_STAGE;
        #pragma unroll
        for (int ks = 0; ks < 2; ks++) {
            const uint32_t kbyte = ks * 32;
            uint32_t aph[2][4], apl[2][4], bvh[4][2], bvl[4][2];
            #pragma unroll
            for (int mi = 0; mi < 2; mi++) {
                const uint32_t ar = st + (a_row + mi * 16) * PV_ROWB + kbyte + a_kb;
                ldm_x4(aph[mi][0], aph[mi][1], aph[mi][2], aph[mi][3], ar);
                ldm_x4(apl[mi][0], apl[mi][1], apl[mi][2], apl[mi][3], ar + PV_A);
            }
            #pragma unroll
            for (int ni = 0; ni < 4; ni++) {
                const uint32_t br = st + 2 * PV_A + (b_row + ni * 8) * PV_ROWB + kbyte + b_kb;
                ldm_x2(bvh[ni][0], bvh[ni][1], br);
                ldm_x2(bvl[ni][0], bvl[ni][1], br + PV_B);
            }
            #pragma unroll
            for (int mi = 0; mi < 2; mi++)
                #pragma unroll
                for (int ni = 0; ni < 4; ni++) {
                    mma_bf16(acc[mi][ni], aph[mi], bvh[ni]);
                    mma_bf16(acc[mi][ni], aph[mi], bvl[ni]);
                    mma_bf16(acc[mi][ni], apl[mi], bvh[ni]);
                }
        }
        __syncthreads();
    }

    const int b = bh >> 4, h = bh & 15;
    const int er = lane >> 2, ec = (lane & 3) * 2;
    #pragma unroll
    for (int mi = 0; mi < 2; mi++) {
        #pragma unroll
        for (int half = 0; half < 2; half++) {
            const int n = i0 + wm * 32 + mi * 16 + er + half * 8;
            #pragma unroll
            for (int ni = 0; ni < 4; ni++) {
                const float v0 = acc[mi][ni][half * 2];
                const float v1 = acc[mi][ni][half * 2 + 1];
                const int d = wn * 32 + ni * 8 + ec;
                const size_t ro = ((size_t)(b * 1024 + n)) * 1024 + h * 64 + d;
                __nv_bfloat16 h0, l0, h1, l1;
                split_bf16(v0, h0, l0);
                split_bf16(v1, h1, l1);
                *(__nv_bfloat162*)&g_ohh[ro] = __nv_bfloat162(h0, h1);
                *(__nv_bfloat162*)&g_ohl[ro] = __nv_bfloat162(l0, l1);
            }
        }
    }
}

// ---------------- K7: scalar outputs -----------------------------------------
__global__ void finalize(float* __restrict__ out,
                         const int* __restrict__ p_flag,
                         const int* __restrict__ p_dcmm) {
    if (threadIdx.x == 0) {
        const float gate = (p_flag[0] != 0 && p_dcmm[0] != 0) ? 1.0f : 0.0f;
        out[4194304] = gate * g_zc * (1.0f / 65536.0f);
        out[4194305] = 0.0f;
        out[4194306] = 0.0f;
    }
}

// ---------------------------------------------------------------------------
extern "C" void kernel_launch(void* const* d_in, const int* in_sizes, int n_in,
                              void* d_out, int out_size) {
    const float* x     = (const float*)d_in[0];
    const float* Wqkv  = (const float*)d_in[1];
    const float* Wproj = (const float*)d_in[2];
    const float* bproj = (const float*)d_in[3];
    const float* Wg    = (const float*)d_in[4];
    const float* bg    = (const float*)d_in[5];
    const float* Wt    = (const float*)d_in[6];
    const float* bt    = (const float*)d_in[7];
    const float* affB  = (const float*)d_in[8];
    const float* cps   = (const float*)d_in[9];
    const int*   flag  = (const int*)d_in[10];
    const int*   dcmm  = (const int*)d_in[12];

    float* out = (float*)d_out;
    float* cp  = out + 4194307;

    cudaFuncSetAttribute(mma_gemm, cudaFuncAttributeMaxDynamicSharedMemorySize, MMA_SMEM);
    cudaFuncSetAttribute(sbias_qk, cudaFuncAttributeMaxDynamicSharedMemorySize, QK_SMEM);
    cudaFuncSetAttribute(pv_mma,   cudaFuncAttributeMaxDynamicSharedMemorySize, PV_SMEM);

    zero_zc_kernel<<<1, 1>>>();
    convert_x<<<4096, 256>>>(x);
    transW<<<dim3(96, 32), dim3(32, 8)>>>(Wqkv, 3072, 0);
    transW<<<dim3(32, 32), dim3(32, 8)>>>(Wproj, 1024, 1);
    mma_gemm<<<dim3(24, 32), 256, MMA_SMEM>>>(nullptr, nullptr, 0);
    vtrans<<<dim3(32, 64), 256>>>();
    zkernel<<<256, 256>>>(Wg, bg, Wt, bt, affB);
    sbias_qk<<<dim3(8, 8, 64), 256, QK_SMEM>>>(cp, cps, flag, dcmm);
    softmax_rows<<<65536, 256>>>();
    pv_mma<<<dim3(8, 64), 256, PV_SMEM>>>();
    mma_gemm<<<dim3(8, 32), 256, MMA_SMEM>>>(bproj, out, 1);
    finalize<<<1, 32>>>(out, flag, dcmm);
}

// round 7
// speedup vs baseline: 2.7949x; 1.1670x over previous
#include <cuda_runtime.h>
#include <cuda_bf16.h>
#include <math.h>
#include <stdint.h>

#define BB 4
#define NTOK 1024
#define CDIM 1024
#define NH 16
#define HD 64
#define KCL 8
#define NBH (BB*NH)
#define NROWS (BB*NH*NTOK)
#define M_ALL (BB*NTOK)

// ---------------- scratch (static device globals) ----------------------------
__device__ float g_q[NROWS*HD];
__device__ __align__(256) float g_z[NROWS*KCL];
__device__ __align__(256) float g_zB[NROWS*KCL];
__device__ __align__(256) float g_th[NROWS];
__device__ float g_zc;
__device__ __align__(256) __nv_bfloat16 g_xh[M_ALL*CDIM];
__device__ __align__(256) __nv_bfloat16 g_xl[M_ALL*CDIM];
__device__ __align__(256) __nv_bfloat16 g_wqh[3072*1024];
__device__ __align__(256) __nv_bfloat16 g_wql[3072*1024];
__device__ __align__(256) __nv_bfloat16 g_wph[1024*1024];
__device__ __align__(256) __nv_bfloat16 g_wpl[1024*1024];
__device__ __align__(256) __nv_bfloat16 g_ohh[M_ALL*CDIM];
__device__ __align__(256) __nv_bfloat16 g_ohl[M_ALL*CDIM];
__device__ __align__(256) __nv_bfloat16 g_qh[NROWS*HD], g_ql[NROWS*HD];
__device__ __align__(256) __nv_bfloat16 g_kh[NROWS*HD], g_kl[NROWS*HD];
__device__ __align__(256) __nv_bfloat16 g_vh[NROWS*HD], g_vl[NROWS*HD];
__device__ __align__(256) __nv_bfloat16 g_vth[NROWS*HD], g_vtl[NROWS*HD];

// ---------------- helpers ----------------------------------------------------
__device__ __forceinline__ uint32_t smem_u32(const void* p) {
    uint32_t a;
    asm("{ .reg .u64 t; cvta.to.shared.u64 t, %1; cvt.u32.u64 %0, t; }"
        : "=r"(a) : "l"(p));
    return a;
}
__device__ __forceinline__ float fast_tanh(float x) {
    float r;
    asm("tanh.approx.f32 %0, %1;" : "=f"(r) : "f"(x));
    return r;
}
#define CP_ASYNC16(dst, src) \
    asm volatile("cp.async.cg.shared.global [%0], [%1], 16;" :: "r"(dst), "l"(src))
#define CP_COMMIT() asm volatile("cp.async.commit_group;" ::: "memory")
#define CP_WAIT(n)  asm volatile("cp.async.wait_group %0;" :: "n"(n) : "memory")

__device__ __forceinline__ void ldm_x4(uint32_t& r0, uint32_t& r1, uint32_t& r2,
                                       uint32_t& r3, uint32_t addr) {
    asm volatile("ldmatrix.sync.aligned.m8n8.x4.shared.b16 {%0,%1,%2,%3}, [%4];"
                 : "=r"(r0), "=r"(r1), "=r"(r2), "=r"(r3) : "r"(addr));
}
__device__ __forceinline__ void ldm_x2(uint32_t& r0, uint32_t& r1, uint32_t addr) {
    asm volatile("ldmatrix.sync.aligned.m8n8.x2.shared.b16 {%0,%1}, [%2];"
                 : "=r"(r0), "=r"(r1) : "r"(addr));
}
__device__ __forceinline__ void mma_bf16(float* c, const uint32_t* a, const uint32_t* b) {
    asm volatile(
        "mma.sync.aligned.m16n8k16.row.col.f32.bf16.bf16.f32 "
        "{%0,%1,%2,%3}, {%4,%5,%6,%7}, {%8,%9}, {%0,%1,%2,%3};"
        : "+f"(c[0]), "+f"(c[1]), "+f"(c[2]), "+f"(c[3])
        : "r"(a[0]), "r"(a[1]), "r"(a[2]), "r"(a[3]), "r"(b[0]), "r"(b[1]));
}
__device__ __forceinline__ void split_bf16(float v, __nv_bfloat16& hi, __nv_bfloat16& lo) {
    hi = __float2bfloat16(v);
    lo = __float2bfloat16(v - __bfloat162float(hi));
}
__device__ __forceinline__ void pack_hl(float x, float y, uint32_t& hi, uint32_t& lo) {
    __nv_bfloat16 hx, lx, hy, ly;
    split_bf16(x, hx, lx);
    split_bf16(y, hy, ly);
    __nv_bfloat162 h2(hx, hy), l2(lx, ly);
    hi = *(uint32_t*)&h2;
    lo = *(uint32_t*)&l2;
}

// ---------------------------------------------------------------------------
__global__ void zero_zc_kernel() { g_zc = 0.0f; }

// ---------------- prep: x -> hi/lo bf16 -------------------------------------
__global__ __launch_bounds__(256) void convert_x(const float* __restrict__ x) {
    int i = (blockIdx.x * 256 + threadIdx.x) * 4;
    float4 v = *(const float4*)&x[i];
    float vals[4] = {v.x, v.y, v.z, v.w};
    __nv_bfloat16 h[4], l[4];
    #pragma unroll
    for (int c = 0; c < 4; c++) split_bf16(vals[c], h[c], l[c]);
    *(__nv_bfloat162*)&g_xh[i]     = __nv_bfloat162(h[0], h[1]);
    *(__nv_bfloat162*)&g_xh[i + 2] = __nv_bfloat162(h[2], h[3]);
    *(__nv_bfloat162*)&g_xl[i]     = __nv_bfloat162(l[0], l[1]);
    *(__nv_bfloat162*)&g_xl[i + 2] = __nv_bfloat162(l[2], l[3]);
}

// ---------------- prep: W[K,N] -> transposed hi/lo bf16 [N,K] ----------------
__global__ void transW(const float* __restrict__ W, int N, int which) {
    __shared__ float s[32][33];
    __nv_bfloat16* Th = which ? g_wph : g_wqh;
    __nv_bfloat16* Tl = which ? g_wpl : g_wql;
    const int n0 = blockIdx.x * 32, k0 = blockIdx.y * 32;
    const int tx = threadIdx.x, ty = threadIdx.y;
    #pragma unroll
    for (int i = 0; i < 4; i++)
        s[ty + i * 8][tx] = W[(size_t)(k0 + ty + i * 8) * N + n0 + tx];
    __syncthreads();
    #pragma unroll
    for (int i = 0; i < 4; i++) {
        int n = ty + i * 8;
        float v = s[tx][n];
        __nv_bfloat16 hh, ll;
        split_bf16(v, hh, ll);
        Th[(size_t)(n0 + n) * 1024 + k0 + tx] = hh;
        Tl[(size_t)(n0 + n) * 1024 + k0 + tx] = ll;
    }
}

// ---------------- tensor-core bf16x3 GEMM, 128x128x32 tiles ------------------
#define ROWB 80
#define TILE_B (128 * ROWB)
#define STAGE_B (4 * TILE_B)
#define MMA_SMEM (2 * STAGE_B)

__device__ __forceinline__ void ld_stage(uint32_t sb, int stage,
        const __nv_bfloat16* __restrict__ Ah, const __nv_bfloat16* __restrict__ Al,
        const __nv_bfloat16* __restrict__ Bh, const __nv_bfloat16* __restrict__ Bl,
        int m0, int n0, int kc, int t) {
    const int row = t >> 2, chunk = t & 3;
    const uint32_t base = sb + stage * STAGE_B;
    const uint32_t soff = row * ROWB + chunk * 16;
    const size_t goffA = (size_t)(m0 + row) * 1024 + kc + chunk * 8;
    const size_t goffB = (size_t)(n0 + row) * 1024 + kc + chunk * 8;
    #pragma unroll
    for (int i = 0; i < 2; i++) {
        const uint32_t so = soff + i * 64 * ROWB;
        const size_t ga = goffA + (size_t)i * 64 * 1024;
        const size_t gb = goffB + (size_t)i * 64 * 1024;
        CP_ASYNC16(base + 0 * TILE_B + so, Ah + ga);
        CP_ASYNC16(base + 1 * TILE_B + so, Al + ga);
        CP_ASYNC16(base + 2 * TILE_B + so, Bh + gb);
        CP_ASYNC16(base + 3 * TILE_B + so, Bl + gb);
    }
}

__global__ __launch_bounds__(256) void mma_gemm(const float* __restrict__ bias,
                                                float* __restrict__ outp, int mode) {
    extern __shared__ char sm[];
    const uint32_t sb = smem_u32(sm);
    const int t = threadIdx.x, wid = t >> 5, lane = t & 31;
    const int wm = wid >> 2, wn = wid & 3;
    const int n0 = blockIdx.x * 128, m0 = blockIdx.y * 128;

    const __nv_bfloat16* Ah = mode ? g_ohh : g_xh;
    const __nv_bfloat16* Al = mode ? g_ohl : g_xl;
    const __nv_bfloat16* Bh = mode ? g_wph : g_wqh;
    const __nv_bfloat16* Bl = mode ? g_wpl : g_wql;

    float acc[4][4][4];
    #pragma unroll
    for (int mi = 0; mi < 4; mi++)
        #pragma unroll
        for (int ni = 0; ni < 4; ni++)
            #pragma unroll
            for (int r = 0; r < 4; r++) acc[mi][ni][r] = 0.0f;

    const uint32_t a_row = wm * 64 + (lane & 15);
    const uint32_t a_kb  = (lane >> 4) * 16;
    const uint32_t b_row = wn * 32 + (lane & 7);
    const uint32_t b_kb  = ((lane >> 3) & 1) * 16;

    ld_stage(sb, 0, Ah, Al, Bh, Bl, m0, n0, 0, t);
    CP_COMMIT();

    for (int kb = 0; kb < 32; kb++) {
        if (kb + 1 < 32) {
            ld_stage(sb, (kb + 1) & 1, Ah, Al, Bh, Bl, m0, n0, (kb + 1) * 32, t);
            CP_COMMIT();
            CP_WAIT(1);
        } else {
            CP_WAIT(0);
        }
        __syncthreads();

        const uint32_t st = sb + (kb & 1) * STAGE_B;
        #pragma unroll
        for (int ks = 0; ks < 2; ks++) {
            const uint32_t kbyte = ks * 32;
            uint32_t afh[4][4], afl[4][4], bfh[4][2], bfl[4][2];
            #pragma unroll
            for (int mi = 0; mi < 4; mi++) {
                const uint32_t ar = st + (a_row + mi * 16) * ROWB + kbyte + a_kb;
                ldm_x4(afh[mi][0], afh[mi][1], afh[mi][2], afh[mi][3], ar);
                ldm_x4(afl[mi][0], afl[mi][1], afl[mi][2], afl[mi][3], ar + TILE_B);
            }
            #pragma unroll
            for (int ni = 0; ni < 4; ni++) {
                const uint32_t br = st + 2 * TILE_B + (b_row + ni * 8) * ROWB + kbyte + b_kb;
                ldm_x2(bfh[ni][0], bfh[ni][1], br);
                ldm_x2(bfl[ni][0], bfl[ni][1], br + TILE_B);
            }
            #pragma unroll
            for (int mi = 0; mi < 4; mi++)
                #pragma unroll
                for (int ni = 0; ni < 4; ni++) {
                    mma_bf16(acc[mi][ni], afh[mi], bfh[ni]);
                    mma_bf16(acc[mi][ni], afh[mi], bfl[ni]);
                    mma_bf16(acc[mi][ni], afl[mi], bfh[ni]);
                }
        }
        __syncthreads();
    }

    const int er = lane >> 2, ec = (lane & 3) * 2;
    #pragma unroll
    for (int mi = 0; mi < 4; mi++) {
        #pragma unroll
        for (int half = 0; half < 2; half++) {
            const int m = m0 + wm * 64 + mi * 16 + er + half * 8;
            #pragma unroll
            for (int ni = 0; ni < 4; ni++) {
                const float v0 = acc[mi][ni][half * 2];
                const float v1 = acc[mi][ni][half * 2 + 1];
                const int col = n0 + wn * 32 + ni * 8 + ec;
                if (mode == 0) {
                    const int b = m >> 10, n = m & 1023;
                    #pragma unroll
                    for (int u = 0; u < 2; u++) {
                        const int c2 = col + u;
                        const int which = c2 >> 10, rem = c2 & 1023;
                        const int hh = rem >> 6, d = rem & 63;
                        const float val = u ? v1 : v0;
                        const size_t idx = (size_t)(((b << 4) + hh) * 1024 + n) * 64 + d;
                        __nv_bfloat16 bhi, blo;
                        split_bf16(val, bhi, blo);
                        if (which == 0) {
                            g_q[idx] = val; g_qh[idx] = bhi; g_ql[idx] = blo;
                        } else if (which == 1) {
                            g_kh[idx] = bhi; g_kl[idx] = blo;
                        } else {
                            g_vh[idx] = bhi; g_vl[idx] = blo;
                        }
                    }
                } else {
                    float2 w = make_float2(v0 + bias[col], v1 + bias[col + 1]);
                    *(float2*)&outp[(size_t)m * 1024 + col] = w;
                }
            }
        }
    }
}

// ---------------- V transpose: [bh][m][d] -> [bh][d][m] ----------------------
__global__ __launch_bounds__(256) void vtrans() {
    __shared__ __nv_bfloat16 s[32][72];
    const int bh = blockIdx.y, m0 = blockIdx.x * 32;
    const int t = threadIdx.x;
    #pragma unroll
    for (int which = 0; which < 2; which++) {
        const __nv_bfloat16* src = which ? g_vl : g_vh;
        __nv_bfloat16* dst = which ? g_vtl : g_vth;
        const int row = t >> 3, c = (t & 7) * 8;
        *(uint4*)&s[row][c] =
            *(const uint4*)&src[((size_t)bh * 1024 + m0 + row) * 64 + c];
        __syncthreads();
        const int d = t >> 2, ms = (t & 3) * 8;
        __nv_bfloat16 tmp[8];
        #pragma unroll
        for (int i = 0; i < 8; i++) tmp[i] = s[ms + i][d];
        *(uint4*)&dst[((size_t)bh * 64 + d) * 1024 + m0 + ms] = *(uint4*)tmp;
        __syncthreads();
    }
}

// ---------------- K2: cluster softmax z, zB, theta ---------------------------
__global__ __launch_bounds__(256) void zkernel(const float* __restrict__ Wg,
                                               const float* __restrict__ bg,
                                               const float* __restrict__ Wt,
                                               const float* __restrict__ bt,
                                               const float* __restrict__ affB) {
    const int r = blockIdx.x * 256 + threadIdx.x;
    const int h = (r >> 10) & (NH - 1);
    const float* q = g_q + r * HD;

    float g[KCL];
    #pragma unroll
    for (int l = 0; l < KCL; l++) g[l] = bg[l];
    float th = bt[0];
    for (int k = 0; k < HD; k++) {
        const float qv = q[k];
        th += qv * Wt[k];
        #pragma unroll
        for (int l = 0; l < KCL; l++) g[l] += qv * Wg[k * KCL + l];
    }
    float mx = g[0];
    #pragma unroll
    for (int l = 1; l < KCL; l++) mx = fmaxf(mx, g[l]);
    float s = 0.0f;
    #pragma unroll
    for (int l = 0; l < KCL; l++) { g[l] = __expf(g[l] - mx); s += g[l]; }
    const float inv = 1.0f / s;
    float ent = 0.0f;
    #pragma unroll
    for (int l = 0; l < KCL; l++) {
        const float z = g[l] * inv;
        g[l] = z;
        ent -= z * logf(z + 1e-8f);
    }
    float zB[KCL];
    #pragma unroll
    for (int l = 0; l < KCL; l++) zB[l] = 0.0f;
    #pragma unroll
    for (int k = 0; k < KCL; k++) {
        const float zk = g[k];
        #pragma unroll
        for (int l = 0; l < KCL; l++) {
            const float a = affB[h * 64 + k * KCL + l];
            zB[l] += zk / (1.0f + __expf(-a));
        }
    }
    g_th[r] = fmaxf(th, 0.0f);
    #pragma unroll
    for (int l = 0; l < KCL; l++) { g_z[r * KCL + l] = g[l]; g_zB[r * KCL + l] = zB[l]; }

    __shared__ float red[256];
    red[threadIdx.x] = ent;
    __syncthreads();
    for (int s2 = 128; s2 > 0; s2 >>= 1) {
        if (threadIdx.x < s2) red[threadIdx.x] += red[threadIdx.x + s2];
        __syncthreads();
    }
    if (threadIdx.x == 0) atomicAdd(&g_zc, red[0]);
}

// ---------------- fused attention: S=QK^T*scale+bias, softmax, O=PV ----------
// smem map (bytes):
//  Qh 0 (18432), Ql 18432
//  K stages at 36864: per stage 36864 (Kh 18432 + Kl 18432), x2
//  V stages at 110592: per stage 34816 (Vh 17408 + Vl 17408), x2   (V^T: [d][tok])
//  zj stages at 180224: 4096 x2
//  thj stages at 188416: 512 x2
//  zBi 189440 (4096), thi 193536 (512)
#define FA_QROWB 144
#define FA_VROWB 272
#define FA_SK    36864
#define FA_SV    110592
#define FA_SZJ   180224
#define FA_STHJ  188416
#define FA_SZBI  189440
#define FA_STHI  193536
#define FA_SMEM  194048

__device__ __forceinline__ void fa_ld_chunk(uint32_t sb, int stage, int bh,
                                            int ch, int t) {
    const uint32_t kbase = sb + FA_SK + stage * 36864;
    const size_t kg = ((size_t)bh * 1024 + ch * 128) * 64;
    #pragma unroll
    for (int i = 0; i < 4; i++) {
        const int u = t + i * 256;
        const int row = u >> 3, c = u & 7;
        const uint32_t so = kbase + row * FA_QROWB + c * 16;
        CP_ASYNC16(so,         g_kh + kg + row * 64 + c * 8);
        CP_ASYNC16(so + 18432, g_kl + kg + row * 64 + c * 8);
    }
    const uint32_t vbase = sb + FA_SV + stage * 34816;
    const size_t vg = (size_t)bh * 64 * 1024 + ch * 128;
    #pragma unroll
    for (int i = 0; i < 4; i++) {
        const int u = t + i * 256;
        const int row = u >> 4, c = u & 15;
        const uint32_t so = vbase + row * FA_VROWB + c * 16;
        CP_ASYNC16(so,         g_vth + vg + (size_t)row * 1024 + c * 8);
        CP_ASYNC16(so + 17408, g_vtl + vg + (size_t)row * 1024 + c * 8);
    }
    {
        const int col = t >> 1, half = t & 1;
        CP_ASYNC16(sb + FA_SZJ + stage * 4096 + col * 32 + half * 16,
                   g_z + ((size_t)bh * 1024 + ch * 128 + col) * 8 + half * 4);
    }
    if (t < 32)
        CP_ASYNC16(sb + FA_STHJ + stage * 512 + t * 16,
                   g_th + (size_t)bh * 1024 + ch * 128 + t * 4);
}

__global__ __launch_bounds__(256, 1) void fused_attn(float* __restrict__ cp_out,
                                                     const float* __restrict__ p_cps,
                                                     const int* __restrict__ p_flag,
                                                     const int* __restrict__ p_dcmm) {
    extern __shared__ char sm[];
    const uint32_t sb = smem_u32(sm);
    const int t = threadIdx.x, wid = t >> 5, lane = t & 31;
    const int bh = blockIdx.x, m0 = blockIdx.y * 128;

    // Q tile (once)
    {
        const size_t qb = ((size_t)bh * 1024 + m0) * 64;
        #pragma unroll
        for (int i = 0; i < 4; i++) {
            const int u = t + i * 256;
            const int row = u >> 3, c = u & 7;
            *(uint4*)(sm + row * FA_QROWB + c * 16) =
                *(const uint4*)(g_qh + qb + row * 64 + c * 8);
            *(uint4*)(sm + 18432 + row * FA_QROWB + c * 16) =
                *(const uint4*)(g_ql + qb + row * 64 + c * 8);
        }
    }
    if (t < 128) {
        ((float*)(sm + FA_STHI))[t] = g_th[(size_t)bh * 1024 + m0 + t];
        #pragma unroll
        for (int l = 0; l < KCL; l++)
            ((float*)(sm + FA_SZBI))[t * 8 + l] =
                g_zB[((size_t)bh * 1024 + m0 + t) * 8 + l];
    }
    fa_ld_chunk(sb, 0, bh, 0, t);
    CP_COMMIT();
    __syncthreads();

    // preload Q fragments (constant over chunks)
    uint32_t aqh[4][4], aql[4][4];
    {
        const uint32_t a_row = wid * 16 + (lane & 15);
        const uint32_t a_kb  = (lane >> 4) * 16;
        #pragma unroll
        for (int ks = 0; ks < 4; ks++) {
            const uint32_t ar = sb + a_row * FA_QROWB + ks * 32 + a_kb;
            ldm_x4(aqh[ks][0], aqh[ks][1], aqh[ks][2], aqh[ks][3], ar);
            ldm_x4(aql[ks][0], aql[ks][1], aql[ks][2], aql[ks][3], ar + 18432);
        }
    }
    // per-thread row constants
    const int er = lane >> 2;
    const int r0 = wid * 16 + er;      // local rows r0, r0+8
    const float gate = (p_flag[0] != 0 && p_dcmm[0] != 0) ? 1.0f : 0.0f;
    const float cps = p_cps[0] * gate;
    float zbr0[KCL], zbr1[KCL];
    #pragma unroll
    for (int l = 0; l < KCL; l++) {
        zbr0[l] = ((float*)(sm + FA_SZBI))[r0 * 8 + l];
        zbr1[l] = ((float*)(sm + FA_SZBI))[(r0 + 8) * 8 + l];
    }
    const float fi0 = cps * ((float*)(sm + FA_STHI))[r0];
    const float fi1 = cps * ((float*)(sm + FA_STHI))[r0 + 8];

    float o[8][4];
    #pragma unroll
    for (int ni = 0; ni < 8; ni++)
        #pragma unroll
        for (int r = 0; r < 4; r++) o[ni][r] = 0.0f;
    float mr0 = -1e30f, mr1 = -1e30f, lr0 = 0.0f, lr1 = 0.0f;

    const uint32_t b_row8 = lane & 7;
    const uint32_t b_kb = ((lane >> 3) & 1) * 16;
    const int c0l = (lane & 3) * 2;
    const long long cpbase = (long long)bh << 20;

    for (int ch = 0; ch < 8; ch++) {
        if (ch < 8 - 1) {
            fa_ld_chunk(sb, (ch + 1) & 1, bh, ch + 1, t);
            CP_COMMIT();
            CP_WAIT(1);
        } else {
            CP_WAIT(0);
        }
        __syncthreads();

        const uint32_t kst = sb + FA_SK + (ch & 1) * 36864;
        const uint32_t vst = sb + FA_SV + (ch & 1) * 34816;
        const float* zjs = (const float*)(sm + FA_SZJ + (ch & 1) * 4096);
        const float* thj = (const float*)(sm + FA_STHJ + (ch & 1) * 512);

        // ---- S = Q K^T (3-pass hi/lo) ----
        float s[16][4];
        #pragma unroll
        for (int ni = 0; ni < 16; ni++)
            #pragma unroll
            for (int r = 0; r < 4; r++) s[ni][r] = 0.0f;

        #pragma unroll
        for (int ks = 0; ks < 4; ks++) {
            #pragma unroll
            for (int ni = 0; ni < 16; ni++) {
                uint32_t bkh[2], bkl[2];
                const uint32_t br = kst + (ni * 8 + b_row8) * FA_QROWB + ks * 32 + b_kb;
                ldm_x2(bkh[0], bkh[1], br);
                ldm_x2(bkl[0], bkl[1], br + 18432);
                mma_bf16(s[ni], aqh[ks], bkh);
                mma_bf16(s[ni], aqh[ks], bkl);
                mma_bf16(s[ni], aql[ks], bkh);
            }
        }

        // ---- bias + cp write + chunk max ----
        float cmax0 = -1e30f, cmax1 = -1e30f;
        #pragma unroll
        for (int ni = 0; ni < 16; ni++) {
            const int c0 = ni * 8 + c0l;
            float d00 = 0.f, d01 = 0.f, d10 = 0.f, d11 = 0.f;
            #pragma unroll
            for (int l = 0; l < KCL; l++) {
                const float z0 = zjs[c0 * 8 + l], z1 = zjs[(c0 + 1) * 8 + l];
                d00 += zbr0[l] * z0; d01 += zbr0[l] * z1;
                d10 += zbr1[l] * z0; d11 += zbr1[l] * z1;
            }
            const float th0 = thj[c0], th1 = thj[c0 + 1];
            const float b00 = fi0 * th0 * fast_tanh(d00);
            const float b01 = fi0 * th1 * fast_tanh(d01);
            const float b10 = fi1 * th0 * fast_tanh(d10);
            const float b11 = fi1 * th1 * fast_tanh(d11);
            const long long off = cpbase + (long long)(m0 + r0) * 1024 + ch * 128 + c0;
            cp_out[off] = b00; cp_out[off + 1] = b01;
            cp_out[off + 8192] = b10; cp_out[off + 8193] = b11;  // row +8 => +8*1024
            s[ni][0] = s[ni][0] * 0.125f + b00;
            s[ni][1] = s[ni][1] * 0.125f + b01;
            s[ni][2] = s[ni][2] * 0.125f + b10;
            s[ni][3] = s[ni][3] * 0.125f + b11;
            cmax0 = fmaxf(cmax0, fmaxf(s[ni][0], s[ni][1]));
            cmax1 = fmaxf(cmax1, fmaxf(s[ni][2], s[ni][3]));
        }
        cmax0 = fmaxf(cmax0, __shfl_xor_sync(0xffffffffu, cmax0, 1));
        cmax0 = fmaxf(cmax0, __shfl_xor_sync(0xffffffffu, cmax0, 2));
        cmax1 = fmaxf(cmax1, __shfl_xor_sync(0xffffffffu, cmax1, 1));
        cmax1 = fmaxf(cmax1, __shfl_xor_sync(0xffffffffu, cmax1, 2));

        const float M0 = fmaxf(mr0, cmax0), M1 = fmaxf(mr1, cmax1);
        const float sc0 = __expf(mr0 - M0), sc1 = __expf(mr1 - M1);
        mr0 = M0; mr1 = M1;

        float ls0 = 0.0f, ls1 = 0.0f;
        #pragma unroll
        for (int ni = 0; ni < 16; ni++) {
            s[ni][0] = __expf(s[ni][0] - M0);
            s[ni][1] = __expf(s[ni][1] - M0);
            s[ni][2] = __expf(s[ni][2] - M1);
            s[ni][3] = __expf(s[ni][3] - M1);
            ls0 += s[ni][0] + s[ni][1];
            ls1 += s[ni][2] + s[ni][3];
        }
        ls0 += __shfl_xor_sync(0xffffffffu, ls0, 1);
        ls0 += __shfl_xor_sync(0xffffffffu, ls0, 2);
        ls1 += __shfl_xor_sync(0xffffffffu, ls1, 1);
        ls1 += __shfl_xor_sync(0xffffffffu, ls1, 2);
        lr0 = lr0 * sc0 + ls0;
        lr1 = lr1 * sc1 + ls1;
        #pragma unroll
        for (int ni = 0; ni < 8; ni++) {
            o[ni][0] *= sc0; o[ni][1] *= sc0;
            o[ni][2] *= sc1; o[ni][3] *= sc1;
        }

        // ---- O += P V (P frags built in registers) ----
        #pragma unroll
        for (int ks = 0; ks < 8; ks++) {
            uint32_t ah[4], al[4];
            pack_hl(s[2 * ks][0],     s[2 * ks][1],     ah[0], al[0]);
            pack_hl(s[2 * ks][2],     s[2 * ks][3],     ah[1], al[1]);
            pack_hl(s[2 * ks + 1][0], s[2 * ks + 1][1], ah[2], al[2]);
            pack_hl(s[2 * ks + 1][2], s[2 * ks + 1][3], ah[3], al[3]);
            #pragma unroll
            for (int ni = 0; ni < 8; ni++) {
                uint32_t bvh[2], bvl[2];
                const uint32_t br = vst + (ni * 8 + b_row8) * FA_VROWB + ks * 32 + b_kb;
                ldm_x2(bvh[0], bvh[1], br);
                ldm_x2(bvl[0], bvl[1], br + 17408);
                mma_bf16(o[ni], ah, bvh);
                mma_bf16(o[ni], ah, bvl);
                mma_bf16(o[ni], al, bvh);
            }
        }
        __syncthreads();
    }

    // ---- finalize O, write hi/lo bf16 ----
    const float inv0 = 1.0f / lr0, inv1 = 1.0f / lr1;
    const int b = bh >> 4, h = bh & 15;
    #pragma unroll
    for (int ni = 0; ni < 8; ni++) {
        const int d = ni * 8 + c0l;
        const size_t ro = ((size_t)(b * 1024 + m0 + r0)) * 1024 + h * 64 + d;
        uint32_t hi, lo;
        pack_hl(o[ni][0] * inv0, o[ni][1] * inv0, hi, lo);
        *(uint32_t*)&g_ohh[ro] = hi;
        *(uint32_t*)&g_ohl[ro] = lo;
        pack_hl(o[ni][2] * inv1, o[ni][3] * inv1, hi, lo);
        *(uint32_t*)&g_ohh[ro + 8 * 1024] = hi;
        *(uint32_t*)&g_ohl[ro + 8 * 1024] = lo;
    }
}

// ---------------- scalar outputs ---------------------------------------------
__global__ void finalize(float* __restrict__ out,
                         const int* __restrict__ p_flag,
                         const int* __restrict__ p_dcmm) {
    if (threadIdx.x == 0) {
        const float gate = (p_flag[0] != 0 && p_dcmm[0] != 0) ? 1.0f : 0.0f;
        out[4194304] = gate * g_zc * (1.0f / 65536.0f);
        out[4194305] = 0.0f;
        out[4194306] = 0.0f;
    }
}

// ---------------------------------------------------------------------------
extern "C" void kernel_launch(void* const* d_in, const int* in_sizes, int n_in,
                              void* d_out, int out_size) {
    const float* x     = (const float*)d_in[0];
    const float* Wqkv  = (const float*)d_in[1];
    const float* Wproj = (const float*)d_in[2];
    const float* bproj = (const float*)d_in[3];
    const float* Wg    = (const float*)d_in[4];
    const float* bg    = (const float*)d_in[5];
    const float* Wt    = (const float*)d_in[6];
    const float* bt    = (const float*)d_in[7];
    const float* affB  = (const float*)d_in[8];
    const float* cps   = (const float*)d_in[9];
    const int*   flag  = (const int*)d_in[10];
    const int*   dcmm  = (const int*)d_in[12];

    float* out = (float*)d_out;
    float* cp  = out + 4194307;

    cudaFuncSetAttribute(mma_gemm, cudaFuncAttributeMaxDynamicSharedMemorySize, MMA_SMEM);
    cudaFuncSetAttribute(fused_attn, cudaFuncAttributeMaxDynamicSharedMemorySize, FA_SMEM);

    zero_zc_kernel<<<1, 1>>>();
    convert_x<<<4096, 256>>>(x);
    transW<<<dim3(96, 32), dim3(32, 8)>>>(Wqkv, 3072, 0);
    transW<<<dim3(32, 32), dim3(32, 8)>>>(Wproj, 1024, 1);
    mma_gemm<<<dim3(24, 32), 256, MMA_SMEM>>>(nullptr, nullptr, 0);
    vtrans<<<dim3(32, 64), 256>>>();
    zkernel<<<256, 256>>>(Wg, bg, Wt, bt, affB);
    fused_attn<<<dim3(64, 8), 256, FA_SMEM>>>(cp, cps, flag, dcmm);
    mma_gemm<<<dim3(8, 32), 256, MMA_SMEM>>>(bproj, out, 1);
    finalize<<<1, 32>>>(out, flag, dcmm);
}